// round 9
// baseline (speedup 1.0000x reference)
#include <cuda_runtime.h>
#include <cuda_bf16.h>
#include <cstdint>

// ---------------- problem constants ----------------
#define DD   1024
#define EE   8
#define HH   2048
#define NN   8192   // B*T tokens

// GEMM tile config: CTA 128x256, 16 warps (4M x 4N), warp tile 32x64, K-chunk 32
#define TM   128
#define TN   256
#define TK   32
#define A_LO 8192
#define B_HI 16384
#define B_LO 32768
#define STAGE_BYTES 49152            // Ahi8K + Alo8K + Bhi16K + Blo16K
#define SMEM_BYTES  (4*STAGE_BYTES + 64)   // 4 stages + full/empty mbarriers

// Tiled-plane geometry:
//  A planes: per (e, mblock, kchunk): 8192B, 128 rows x 64B, swizzled
//  B planes: per (e, nblock, kchunk): 16384B, 256 rows x 64B, swizzled
//  row byte: m*64 + ((u ^ ((m>>1)&3))<<4) + (k&7)*2,  u = (k>>3)&3

// ---------------- static device scratch ----------------
__device__ int   g_cnt[EE];
__device__ int   g_tok[EE * NN];
__device__ float g_gate[EE * NN];
__device__ __nv_bfloat16 g_xg_hi[(size_t)EE * NN * DD];   // [e][mb<64][kc<32][8KB]
__device__ __nv_bfloat16 g_xg_lo[(size_t)EE * NN * DD];
__device__ __nv_bfloat16 g_h_hi [(size_t)EE * NN * HH];   // [e][mb<64][kc<64][8KB]
__device__ __nv_bfloat16 g_h_lo [(size_t)EE * NN * HH];
__device__ __nv_bfloat16 g_w1t_hi[(size_t)EE * DD * HH];  // [e][nb<8][kc<32][16KB]
__device__ __nv_bfloat16 g_w1t_lo[(size_t)EE * DD * HH];
__device__ __nv_bfloat16 g_w2t_hi[(size_t)EE * HH * DD];  // [e][nb<4][kc<64][16KB]
__device__ __nv_bfloat16 g_w2t_lo[(size_t)EE * HH * DD];

// ---------------- helpers ----------------
__device__ __forceinline__ uint32_t smem_u32(const void* p) {
    uint32_t a;
    asm("{ .reg .u64 t; cvta.to.shared.u64 t, %1; cvt.u32.u64 %0, t; }" : "=r"(a) : "l"(p));
    return a;
}
__device__ __forceinline__ void ldsm4(uint32_t* r, uint32_t a) {
    asm volatile("ldmatrix.sync.aligned.m8n8.x4.shared.b16 {%0,%1,%2,%3}, [%4];"
                 : "=r"(r[0]), "=r"(r[1]), "=r"(r[2]), "=r"(r[3]) : "r"(a));
}
__device__ __forceinline__ void mma16816(float* c, const uint32_t* a, uint32_t b0, uint32_t b1) {
    asm volatile("mma.sync.aligned.m16n8k16.row.col.f32.bf16.bf16.f32 "
                 "{%0,%1,%2,%3}, {%4,%5,%6,%7}, {%8,%9}, {%0,%1,%2,%3};"
                 : "+f"(c[0]), "+f"(c[1]), "+f"(c[2]), "+f"(c[3])
                 : "r"(a[0]), "r"(a[1]), "r"(a[2]), "r"(a[3]), "r"(b0), "r"(b1));
}
__device__ __forceinline__ uint32_t pack2(float a, float b) {
    __nv_bfloat16 h0 = __float2bfloat16(a), h1 = __float2bfloat16(b);
    return (uint32_t)__bfloat16_as_ushort(h0) | ((uint32_t)__bfloat16_as_ushort(h1) << 16);
}
#define MBAR_INIT(a, c) asm volatile("mbarrier.init.shared.b64 [%0], %1;" :: "r"(a), "r"((uint32_t)(c)) : "memory")
#define MBAR_EXPECT_TX(a, tx) asm volatile("mbarrier.arrive.expect_tx.shared.b64 _, [%0], %1;" :: "r"(a), "r"((uint32_t)(tx)) : "memory")
#define MBAR_ARRIVE(a) asm volatile("mbarrier.arrive.release.cta.shared::cta.b64 _, [%0];" :: "r"(a) : "memory")
#define MBAR_WAIT(a, ph) do { \
    uint32_t _m = (a); uint32_t _p = (uint32_t)(ph); uint32_t _d; \
    asm volatile("{\n\t.reg .pred p;\n\tmbarrier.try_wait.parity.acquire.cta.shared::cta.b64 p, [%1], %2;\n\tselp.b32 %0,1,0,p;\n\t}" \
        : "=r"(_d) : "r"(_m), "r"(_p) : "memory"); \
    if (!_d) { \
        asm volatile("{\n\t.reg .pred P1;\n\tWL_%=:\n\tmbarrier.try_wait.parity.acquire.cta.shared::cta.b64 P1, [%0], %1, 0x989680;\n\t@P1 bra.uni WD_%=;\n\tbra.uni WL_%=;\n\tWD_%=:\n\t}" \
            :: "r"(_m), "r"(_p) : "memory"); \
    } } while (0)
__device__ __forceinline__ void bulk_g2s(uint32_t dst, const void* src, uint32_t bytes, uint32_t mbar) {
    asm volatile("cp.async.bulk.shared::cta.global.mbarrier::complete_tx::bytes [%0], [%1], %2, [%3];"
                 :: "r"(dst), "l"(src), "r"(bytes), "r"(mbar) : "memory");
}

// pack 8 floats -> 16B hi plane + 16B lo plane
__device__ __forceinline__ void split8(const float* v, uint4& hi, uint4& lo) {
    uint32_t h[4], l[4];
#pragma unroll
    for (int i = 0; i < 4; i++) {
        __nv_bfloat16 a = __float2bfloat16(v[2*i]), b = __float2bfloat16(v[2*i+1]);
        h[i] = (uint32_t)__bfloat16_as_ushort(a) | ((uint32_t)__bfloat16_as_ushort(b) << 16);
        l[i] = pack2(v[2*i] - __bfloat162float(a), v[2*i+1] - __bfloat162float(b));
    }
    hi = make_uint4(h[0], h[1], h[2], h[3]);
    lo = make_uint4(l[0], l[1], l[2], l[3]);
}

// ---------------------------------------------------------------------------
// Kernel 0: zero output + reset counters
// ---------------------------------------------------------------------------
__global__ void zero_kernel(float4* __restrict__ out) {
    int i = blockIdx.x * blockDim.x + threadIdx.x;
    out[i] = make_float4(0.f, 0.f, 0.f, 0.f);
    if (blockIdx.x == 0 && threadIdx.x < EE) g_cnt[threadIdx.x] = 0;
}

// ---------------------------------------------------------------------------
// Kernel 1: router (fp32, validated)
// ---------------------------------------------------------------------------
__global__ __launch_bounds__(256) void router_kernel(const float* __restrict__ x,
                                                     const float* __restrict__ rw) {
    int n = blockIdx.x, tid = threadIdx.x;
    const float* xr = x + (size_t)n * DD;
    float acc[EE];
#pragma unroll
    for (int e = 0; e < EE; e++) acc[e] = 0.f;
    for (int i = tid; i < DD; i += 256) {
        float xv = xr[i];
#pragma unroll
        for (int e = 0; e < EE; e++) acc[e] += xv * rw[e * DD + i];
    }
#pragma unroll
    for (int e = 0; e < EE; e++)
#pragma unroll
        for (int o = 16; o > 0; o >>= 1) acc[e] += __shfl_down_sync(0xffffffffu, acc[e], o);

    __shared__ float sm[8][EE];
    int warp = tid >> 5, lane = tid & 31;
    if (lane == 0)
#pragma unroll
        for (int e = 0; e < EE; e++) sm[warp][e] = acc[e];
    __syncthreads();

    if (tid == 0) {
        float logits[EE];
#pragma unroll
        for (int e = 0; e < EE; e++) {
            float s = 0.f;
#pragma unroll
            for (int w = 0; w < 8; w++) s += sm[w][e];
            logits[e] = s;
        }
        int i0 = 0; float v0 = logits[0];
#pragma unroll
        for (int e = 1; e < EE; e++) if (logits[e] > v0) { v0 = logits[e]; i0 = e; }
        int i1 = 0; float v1 = -3.0e38f;
#pragma unroll
        for (int e = 0; e < EE; e++) if (e != i0 && logits[e] > v1) { v1 = logits[e]; i1 = e; }
        float ex = __expf(v1 - v0);
        float g0 = 1.f / (1.f + ex);
        float g1 = ex * g0;
        int p0 = atomicAdd(&g_cnt[i0], 1);
        g_tok[i0 * NN + p0] = n;  g_gate[i0 * NN + p0] = g0;
        int p1 = atomicAdd(&g_cnt[i1], 1);
        g_tok[i1 * NN + p1] = n;  g_gate[i1 * NN + p1] = g1;
    }
}

// ---------------------------------------------------------------------------
// Kernel 2: gather tokens, split hi/lo into swizzled tiled A planes
// ---------------------------------------------------------------------------
__global__ __launch_bounds__(128) void gather_kernel(const float* __restrict__ x) {
    int e = blockIdx.y, slot = blockIdx.x;
    int cnt = g_cnt[e];
    int pad = (cnt + 127) & ~127;  if (pad > NN) pad = NN;
    if (slot >= pad) return;
    int mb = slot >> 7, m = slot & 127;
    int t = threadIdx.x;
    int kc = t >> 2, u = t & 3;
    size_t plane = (((size_t)e * 64 + mb) * 32 + kc) * 8192;
    uint32_t off = (uint32_t)m * 64 + (uint32_t)((u ^ ((m >> 1) & 3)) << 4);
    uint8_t* dh = (uint8_t*)g_xg_hi + plane + off;
    uint8_t* dl = (uint8_t*)g_xg_lo + plane + off;
    if (slot < cnt) {
        int tok = g_tok[e * NN + slot];
        const float4* xs = (const float4*)(x + (size_t)tok * DD + t * 8);
        float v[8];
        float4 a = xs[0], b = xs[1];
        v[0]=a.x; v[1]=a.y; v[2]=a.z; v[3]=a.w; v[4]=b.x; v[5]=b.y; v[6]=b.z; v[7]=b.w;
        uint4 hi, lo;
        split8(v, hi, lo);
        *(uint4*)dh = hi;
        *(uint4*)dl = lo;
    } else {
        uint4 z = make_uint4(0,0,0,0);
        *(uint4*)dh = z;
        *(uint4*)dl = z;
    }
}

// ---------------------------------------------------------------------------
// Kernels 3/4: weights -> transposed, split, swizzled tiled B planes
// ---------------------------------------------------------------------------
template<int R, int C, int WHICH>
__global__ __launch_bounds__(256) void wsplit_kernel(const float* __restrict__ w) {
    int kc = blockIdx.x, nb = blockIdx.y, e = blockIdx.z;
    const float* src = w + (size_t)e * R * C;
    int t = threadIdx.x;
    int n = nb * 256 + t;
    float vals[32];
#pragma unroll
    for (int j = 0; j < 32; j++)
        vals[j] = src[(size_t)(kc * 32 + j) * C + n];
    __nv_bfloat16* hi = (WHICH == 0) ? g_w1t_hi : g_w2t_hi;
    __nv_bfloat16* lo = (WHICH == 0) ? g_w1t_lo : g_w2t_lo;
    size_t plane = (((size_t)e * (C / 256) + nb) * (R / 32) + kc) * 16384;
    int sw = (t >> 1) & 3;
    uint32_t rbase = (uint32_t)t * 64;
#pragma unroll
    for (int u = 0; u < 4; u++) {
        uint4 h4, l4;
        split8(vals + u * 8, h4, l4);
        uint32_t off = rbase + (uint32_t)((u ^ sw) << 4);
        *(uint4*)((uint8_t*)hi + plane + off) = h4;
        *(uint4*)((uint8_t*)lo + plane + off) = l4;
    }
}

// ---------------------------------------------------------------------------
// bulk-fed mma.sync grouped GEMM with producer/consumer mbarrier dataflow.
// D[128x256] += A * B^T, bf16 hi/lo 3-pass. 512 threads (16 warps, 4Mx4N).
// full[s]: tx-tracked load completion; empty[s]: 16 per-warp read-done arrivals.
// Warp-rotated B-tile order desyncs LSU/tensor bursts; empty-arrive placed
// right after the warp's last smem read of the stage.
// ---------------------------------------------------------------------------
template<int KTOT, int KSLICES, bool IS_G1>
__global__ __launch_bounds__(512, 1) void gemm_mma(float* __restrict__ out) {
    constexpr int KCA = KTOT / 32;
    constexpr int KC  = (KTOT / KSLICES) / TK;
    constexpr int NB  = (IS_G1 ? HH : DD) / TN;
    int zz = blockIdx.z;
    int e = zz & (EE - 1);
    int slice = zz >> 3;
    int kc0 = slice * KC;
    int cnt = g_cnt[e];
    int m0  = blockIdx.y * TM;
    if (m0 >= cnt) return;
    int mb  = blockIdx.y;
    int nb  = blockIdx.x;
    int n0  = nb * TN;

    extern __shared__ char smem[];
    uint32_t sb = smem_u32(smem);
    uint32_t fullb  = sb + 4 * STAGE_BYTES;        // 4 x 8B
    uint32_t emptyb = fullb + 32;                  // 4 x 8B

    const uint8_t *pAh, *pAl, *pBh, *pBl;
    {
        size_t ap = (((size_t)e * 64 + mb) * KCA) * 8192;
        size_t bp = (((size_t)e * NB + nb) * KCA) * 16384;
        if (IS_G1) {
            pAh = (const uint8_t*)g_xg_hi + ap;  pAl = (const uint8_t*)g_xg_lo + ap;
            pBh = (const uint8_t*)g_w1t_hi + bp; pBl = (const uint8_t*)g_w1t_lo + bp;
        } else {
            pAh = (const uint8_t*)g_h_hi + ap;   pAl = (const uint8_t*)g_h_lo + ap;
            pBh = (const uint8_t*)g_w2t_hi + bp; pBl = (const uint8_t*)g_w2t_lo + bp;
        }
    }

    int tid = threadIdx.x;
    if (tid == 0) {
#pragma unroll
        for (int s = 0; s < 4; s++) {
            MBAR_INIT(fullb + s * 8, 1);
            MBAR_INIT(emptyb + s * 8, 16);
        }
    }
    __syncthreads();

    auto issue = [&](int j) {
        int s = j & 3;
        uint32_t st = sb + (uint32_t)s * STAGE_BYTES;
        uint32_t mb_s = fullb + s * 8;
        size_t kc = (size_t)(kc0 + j);
        MBAR_EXPECT_TX(mb_s, STAGE_BYTES);
        bulk_g2s(st,        pAh + kc * 8192, 8192, mb_s);
        bulk_g2s(st + A_LO, pAl + kc * 8192, 8192, mb_s);
        bulk_g2s(st + B_HI, pBh + kc * 16384, 16384, mb_s);
        bulk_g2s(st + B_LO, pBl + kc * 16384, 16384, mb_s);
    };
    if (tid == 480) {                 // producer = warp 15 lane 0 (hi-wid priority)
#pragma unroll
        for (int j0 = 0; j0 < 4; j0++) if (j0 < KC) issue(j0);
    }

    // ---- warp / lane geometry ----
    int wid = tid >> 5, lane = tid & 31;
    int wm = wid & 3;
    int wn = wid >> 2;
    int li = lane >> 3;
    int lr = lane & 7;
    int kadd = li >> 1;
    int rsel = (li & 1) * 8 + lr;

    uint32_t abase[2]; int asw[2];
#pragma unroll
    for (int mt = 0; mt < 2; mt++) {
        int m = wm * 32 + mt * 16 + rsel;
        abase[mt] = (uint32_t)m * 64;
        asw[mt] = (m >> 1) & 3;
    }
    uint32_t bbase[4]; int bsw[4];
#pragma unroll
    for (int p = 0; p < 4; p++) {
        int n = wn * 64 + p * 16 + rsel;
        bbase[p] = (uint32_t)n * 64;
        bsw[p] = (n >> 1) & 3;
    }

    float acc[2][8][4];
#pragma unroll
    for (int a = 0; a < 2; a++)
#pragma unroll
        for (int b = 0; b < 8; b++)
#pragma unroll
            for (int c = 0; c < 4; c++) acc[a][b][c] = 0.f;

    for (int j = 0; j < KC; j++) {
        int s = j & 3;
        uint32_t ph = (j >> 2) & 1;
        MBAR_WAIT(fullb + s * 8, ph);
        uint32_t st = sb + (uint32_t)s * STAGE_BYTES;
#pragma unroll
        for (int kqi = 0; kqi < 2; kqi++) {
            int kq = kqi * 2;
            uint32_t ahi[2][4], alo[2][4];
#pragma unroll
            for (int mt = 0; mt < 2; mt++) {
                uint32_t off = abase[mt] + (uint32_t)((((kq + kadd) ^ asw[mt])) << 4);
                ldsm4(ahi[mt], st + off);
                ldsm4(alo[mt], st + A_LO + off);
            }
#pragma unroll
            for (int pi = 0; pi < 4; pi++) {
                int p = (pi + wn) & 3;               // warp-rotated tile order
                uint32_t bh[4], bl[4];
                uint32_t off = bbase[p] + (uint32_t)((((kq + kadd) ^ bsw[p])) << 4);
                ldsm4(bh, st + B_HI + off);
                ldsm4(bl, st + B_LO + off);
                // last smem read of this stage: release it before the MMA tail
                if (kqi == 1 && pi == 3 && lane == 0) MBAR_ARRIVE(emptyb + s * 8);
#pragma unroll
                for (int mt = 0; mt < 2; mt++) {
#pragma unroll
                    for (int sgl = 0; sgl < 2; sgl++) {
                        float* c = acc[mt][p * 2 + sgl];
                        mma16816(c, ahi[mt], bh[sgl], bh[2 + sgl]);
                        mma16816(c, ahi[mt], bl[sgl], bl[2 + sgl]);
                        mma16816(c, alo[mt], bh[sgl], bh[2 + sgl]);
                    }
                }
            }
        }
        // producer: re-issue stage s for chunk j+4 once ALL warps released it
        if (tid == 480 && j + 4 < KC) {
            MBAR_WAIT(emptyb + s * 8, ph);
            issue(j + 4);
        }
    }

    // ---- epilogue ----
    int r4 = lane >> 2, cpair = (lane & 3) * 2;
    if (IS_G1) {
        size_t planeH0 = (((size_t)e * 64 + mb) * 64) * 8192;
#pragma unroll
        for (int mt = 0; mt < 2; mt++) {
#pragma unroll
            for (int q = 0; q < 8; q++) {
                int kcH = (n0 >> 5) + wn * 2 + (q >> 2);
                int u = q & 3;
#pragma unroll
                for (int half = 0; half < 2; half++) {
                    int lm = wm * 32 + mt * 16 + r4 + half * 8;
                    float v0 = acc[mt][q][half * 2 + 0];
                    float v1 = acc[mt][q][half * 2 + 1];
                    v0 = fmaxf(v0, 0.f); v0 *= v0;
                    v1 = fmaxf(v1, 0.f); v1 *= v1;
                    __nv_bfloat16 h0 = __float2bfloat16(v0), h1 = __float2bfloat16(v1);
                    uint32_t hw = (uint32_t)__bfloat16_as_ushort(h0) |
                                  ((uint32_t)__bfloat16_as_ushort(h1) << 16);
                    uint32_t lw = pack2(v0 - __bfloat162float(h0), v1 - __bfloat162float(h1));
                    size_t off = planeH0 + (size_t)kcH * 8192 +
                                 (uint32_t)(lm * 64 + ((u ^ ((lm >> 1) & 3)) << 4) + cpair * 2);
                    *(uint32_t*)((uint8_t*)g_h_hi + off) = hw;
                    *(uint32_t*)((uint8_t*)g_h_lo + off) = lw;
                }
            }
        }
    } else {
#pragma unroll
        for (int mt = 0; mt < 2; mt++) {
            int gm = m0 + wm * 32 + mt * 16;
            int   tokh[2];
            float gth[2];
#pragma unroll
            for (int half = 0; half < 2; half++) {
                int slot = gm + r4 + half * 8;
                bool ok = slot < cnt;
                tokh[half] = ok ? g_tok[e * NN + slot] : -1;
                gth[half]  = ok ? g_gate[e * NN + slot] : 0.f;
            }
#pragma unroll
            for (int q = 0; q < 8; q++) {
                int gn = n0 + wn * 64 + q * 8 + cpair;
#pragma unroll
                for (int half = 0; half < 2; half++) {
                    if (tokh[half] >= 0) {
                        float* orow = out + (size_t)tokh[half] * DD + gn;
                        atomicAdd(orow,     gth[half] * acc[mt][q][half * 2 + 0]);
                        atomicAdd(orow + 1, gth[half] * acc[mt][q][half * 2 + 1]);
                    }
                }
            }
        }
    }
}

// ---------------------------------------------------------------------------
extern "C" void kernel_launch(void* const* d_in, const int* in_sizes, int n_in,
                              void* d_out, int out_size) {
    const float* x  = (const float*)d_in[0];   // (B,T,D)
    const float* rw = (const float*)d_in[1];   // (E,D)
    const float* w1 = (const float*)d_in[2];   // (E,D,H)
    const float* w2 = (const float*)d_in[3];   // (E,H,D)
    float* out = (float*)d_out;                // (B,T,D) fp32

    cudaFuncSetAttribute(gemm_mma<DD, 1, true>,  cudaFuncAttributeMaxDynamicSharedMemorySize, SMEM_BYTES);
    cudaFuncSetAttribute(gemm_mma<HH, 2, false>, cudaFuncAttributeMaxDynamicSharedMemorySize, SMEM_BYTES);

    int zblocks = out_size / (4 * 256);
    zero_kernel<<<zblocks, 256>>>((float4*)out);
    router_kernel<<<NN, 256>>>(x, rw);
    wsplit_kernel<DD, HH, 0><<<dim3(DD / 32, HH / 256, EE), 256>>>(w1);
    wsplit_kernel<HH, DD, 1><<<dim3(HH / 32, DD / 256, EE), 256>>>(w2);
    gather_kernel<<<dim3(NN, EE), 128>>>(x);
    gemm_mma<DD, 1, true><<<dim3(HH / TN, NN / TM, EE), 512, SMEM_BYTES>>>(nullptr);
    gemm_mma<HH, 2, false><<<dim3(DD / TN, NN / TM, EE * 2), 512, SMEM_BYTES>>>(out);
}

// round 10
// speedup vs baseline: 2.6110x; 2.6110x over previous
#include <cuda_runtime.h>
#include <cuda_bf16.h>
#include <cstdint>

// ---------------- problem constants ----------------
#define DD   1024
#define EE   8
#define HH   2048
#define NN   8192   // B*T tokens

// GEMM tile config: CTA 128x256, 16 warps (4M x 4N), warp tile 32x64, K-chunk 32
#define TM   128
#define TN   256
#define TK   32
#define A_LO 8192
#define B_HI 16384
#define B_LO 32768
#define STAGE_BYTES 49152            // Ahi8K + Alo8K + Bhi16K + Blo16K
#define SMEM_BYTES  (4*STAGE_BYTES + 64)   // 4 stages + full/empty mbarriers

// Tiled-plane geometry:
//  A planes: per (e, mblock, kchunk): 8192B, 128 rows x 64B, swizzled
//  B planes: per (e, nblock, kchunk): 16384B, 256 rows x 64B, swizzled
//  row byte: m*64 + ((u ^ ((m>>1)&3))<<4) + (k&7)*2,  u = (k>>3)&3

// ---------------- static device scratch ----------------
__device__ int   g_cnt[EE];
__device__ int   g_tok[EE * NN];
__device__ float g_gate[EE * NN];
__device__ __nv_bfloat16 g_xg_hi[(size_t)EE * NN * DD];   // [e][mb<64][kc<32][8KB]
__device__ __nv_bfloat16 g_xg_lo[(size_t)EE * NN * DD];
__device__ __nv_bfloat16 g_h_hi [(size_t)EE * NN * HH];   // [e][mb<64][kc<64][8KB]
__device__ __nv_bfloat16 g_h_lo [(size_t)EE * NN * HH];
__device__ __nv_bfloat16 g_w1t_hi[(size_t)EE * DD * HH];  // [e][nb<8][kc<32][16KB]
__device__ __nv_bfloat16 g_w1t_lo[(size_t)EE * DD * HH];
__device__ __nv_bfloat16 g_w2t_hi[(size_t)EE * HH * DD];  // [e][nb<4][kc<64][16KB]
__device__ __nv_bfloat16 g_w2t_lo[(size_t)EE * HH * DD];

// ---------------- helpers ----------------
__device__ __forceinline__ uint32_t smem_u32(const void* p) {
    uint32_t a;
    asm("{ .reg .u64 t; cvta.to.shared.u64 t, %1; cvt.u32.u64 %0, t; }" : "=r"(a) : "l"(p));
    return a;
}
__device__ __forceinline__ void ldsm4(uint32_t* r, uint32_t a) {
    asm volatile("ldmatrix.sync.aligned.m8n8.x4.shared.b16 {%0,%1,%2,%3}, [%4];"
                 : "=r"(r[0]), "=r"(r[1]), "=r"(r[2]), "=r"(r[3]) : "r"(a));
}
__device__ __forceinline__ void mma16816(float* c, const uint32_t* a, uint32_t b0, uint32_t b1) {
    asm volatile("mma.sync.aligned.m16n8k16.row.col.f32.bf16.bf16.f32 "
                 "{%0,%1,%2,%3}, {%4,%5,%6,%7}, {%8,%9}, {%0,%1,%2,%3};"
                 : "+f"(c[0]), "+f"(c[1]), "+f"(c[2]), "+f"(c[3])
                 : "r"(a[0]), "r"(a[1]), "r"(a[2]), "r"(a[3]), "r"(b0), "r"(b1));
}
__device__ __forceinline__ uint32_t pack2(float a, float b) {
    __nv_bfloat16 h0 = __float2bfloat16(a), h1 = __float2bfloat16(b);
    return (uint32_t)__bfloat16_as_ushort(h0) | ((uint32_t)__bfloat16_as_ushort(h1) << 16);
}
#define MBAR_INIT(a, c) asm volatile("mbarrier.init.shared.b64 [%0], %1;" :: "r"(a), "r"((uint32_t)(c)) : "memory")
#define MBAR_EXPECT_TX(a, tx) asm volatile("mbarrier.arrive.expect_tx.shared.b64 _, [%0], %1;" :: "r"(a), "r"((uint32_t)(tx)) : "memory")
#define MBAR_ARRIVE_REL(a) asm volatile("mbarrier.arrive.release.cta.shared::cta.b64 _, [%0];" :: "r"(a) : "memory")
#define MBAR_WAIT(a, ph) do { \
    uint32_t _m = (a); uint32_t _p = (uint32_t)(ph); uint32_t _d; \
    asm volatile("{\n\t.reg .pred p;\n\tmbarrier.try_wait.parity.acquire.cta.shared::cta.b64 p, [%1], %2;\n\tselp.b32 %0,1,0,p;\n\t}" \
        : "=r"(_d) : "r"(_m), "r"(_p) : "memory"); \
    if (!_d) { \
        asm volatile("{\n\t.reg .pred P1;\n\tWL_%=:\n\tmbarrier.try_wait.parity.acquire.cta.shared::cta.b64 P1, [%0], %1, 0x989680;\n\t@P1 bra.uni WD_%=;\n\tbra.uni WL_%=;\n\tWD_%=:\n\t}" \
            :: "r"(_m), "r"(_p) : "memory"); \
    } } while (0)
__device__ __forceinline__ void bulk_g2s(uint32_t dst, const void* src, uint32_t bytes, uint32_t mbar) {
    asm volatile("cp.async.bulk.shared::cta.global.mbarrier::complete_tx::bytes [%0], [%1], %2, [%3];"
                 :: "r"(dst), "l"(src), "r"(bytes), "r"(mbar) : "memory");
}

// pack 8 floats -> 16B hi plane + 16B lo plane
__device__ __forceinline__ void split8(const float* v, uint4& hi, uint4& lo) {
    uint32_t h[4], l[4];
#pragma unroll
    for (int i = 0; i < 4; i++) {
        __nv_bfloat16 a = __float2bfloat16(v[2*i]), b = __float2bfloat16(v[2*i+1]);
        h[i] = (uint32_t)__bfloat16_as_ushort(a) | ((uint32_t)__bfloat16_as_ushort(b) << 16);
        l[i] = pack2(v[2*i] - __bfloat162float(a), v[2*i+1] - __bfloat162float(b));
    }
    hi = make_uint4(h[0], h[1], h[2], h[3]);
    lo = make_uint4(l[0], l[1], l[2], l[3]);
}

// ---------------------------------------------------------------------------
// Kernel 0: zero output + reset counters
// ---------------------------------------------------------------------------
__global__ void zero_kernel(float4* __restrict__ out) {
    int i = blockIdx.x * blockDim.x + threadIdx.x;
    out[i] = make_float4(0.f, 0.f, 0.f, 0.f);
    if (blockIdx.x == 0 && threadIdx.x < EE) g_cnt[threadIdx.x] = 0;
}

// ---------------------------------------------------------------------------
// Kernel 1: router (fp32, validated)
// ---------------------------------------------------------------------------
__global__ __launch_bounds__(256) void router_kernel(const float* __restrict__ x,
                                                     const float* __restrict__ rw) {
    int n = blockIdx.x, tid = threadIdx.x;
    const float* xr = x + (size_t)n * DD;
    float acc[EE];
#pragma unroll
    for (int e = 0; e < EE; e++) acc[e] = 0.f;
    for (int i = tid; i < DD; i += 256) {
        float xv = xr[i];
#pragma unroll
        for (int e = 0; e < EE; e++) acc[e] += xv * rw[e * DD + i];
    }
#pragma unroll
    for (int e = 0; e < EE; e++)
#pragma unroll
        for (int o = 16; o > 0; o >>= 1) acc[e] += __shfl_down_sync(0xffffffffu, acc[e], o);

    __shared__ float sm[8][EE];
    int warp = tid >> 5, lane = tid & 31;
    if (lane == 0)
#pragma unroll
        for (int e = 0; e < EE; e++) sm[warp][e] = acc[e];
    __syncthreads();

    if (tid == 0) {
        float logits[EE];
#pragma unroll
        for (int e = 0; e < EE; e++) {
            float s = 0.f;
#pragma unroll
            for (int w = 0; w < 8; w++) s += sm[w][e];
            logits[e] = s;
        }
        int i0 = 0; float v0 = logits[0];
#pragma unroll
        for (int e = 1; e < EE; e++) if (logits[e] > v0) { v0 = logits[e]; i0 = e; }
        int i1 = 0; float v1 = -3.0e38f;
#pragma unroll
        for (int e = 0; e < EE; e++) if (e != i0 && logits[e] > v1) { v1 = logits[e]; i1 = e; }
        float ex = __expf(v1 - v0);
        float g0 = 1.f / (1.f + ex);
        float g1 = ex * g0;
        int p0 = atomicAdd(&g_cnt[i0], 1);
        g_tok[i0 * NN + p0] = n;  g_gate[i0 * NN + p0] = g0;
        int p1 = atomicAdd(&g_cnt[i1], 1);
        g_tok[i1 * NN + p1] = n;  g_gate[i1 * NN + p1] = g1;
    }
}

// ---------------------------------------------------------------------------
// Kernel 2: gather tokens, split hi/lo into swizzled tiled A planes
// ---------------------------------------------------------------------------
__global__ __launch_bounds__(128) void gather_kernel(const float* __restrict__ x) {
    int e = blockIdx.y, slot = blockIdx.x;
    int cnt = g_cnt[e];
    int pad = (cnt + 127) & ~127;  if (pad > NN) pad = NN;
    if (slot >= pad) return;
    int mb = slot >> 7, m = slot & 127;
    int t = threadIdx.x;
    int kc = t >> 2, u = t & 3;
    size_t plane = (((size_t)e * 64 + mb) * 32 + kc) * 8192;
    uint32_t off = (uint32_t)m * 64 + (uint32_t)((u ^ ((m >> 1) & 3)) << 4);
    uint8_t* dh = (uint8_t*)g_xg_hi + plane + off;
    uint8_t* dl = (uint8_t*)g_xg_lo + plane + off;
    if (slot < cnt) {
        int tok = g_tok[e * NN + slot];
        const float4* xs = (const float4*)(x + (size_t)tok * DD + t * 8);
        float v[8];
        float4 a = xs[0], b = xs[1];
        v[0]=a.x; v[1]=a.y; v[2]=a.z; v[3]=a.w; v[4]=b.x; v[5]=b.y; v[6]=b.z; v[7]=b.w;
        uint4 hi, lo;
        split8(v, hi, lo);
        *(uint4*)dh = hi;
        *(uint4*)dl = lo;
    } else {
        uint4 z = make_uint4(0,0,0,0);
        *(uint4*)dh = z;
        *(uint4*)dl = z;
    }
}

// ---------------------------------------------------------------------------
// Kernels 3/4: weights -> transposed, split, swizzled tiled B planes
// ---------------------------------------------------------------------------
template<int R, int C, int WHICH>
__global__ __launch_bounds__(256) void wsplit_kernel(const float* __restrict__ w) {
    int kc = blockIdx.x, nb = blockIdx.y, e = blockIdx.z;
    const float* src = w + (size_t)e * R * C;
    int t = threadIdx.x;
    int n = nb * 256 + t;
    float vals[32];
#pragma unroll
    for (int j = 0; j < 32; j++)
        vals[j] = src[(size_t)(kc * 32 + j) * C + n];
    __nv_bfloat16* hi = (WHICH == 0) ? g_w1t_hi : g_w2t_hi;
    __nv_bfloat16* lo = (WHICH == 0) ? g_w1t_lo : g_w2t_lo;
    size_t plane = (((size_t)e * (C / 256) + nb) * (R / 32) + kc) * 16384;
    int sw = (t >> 1) & 3;
    uint32_t rbase = (uint32_t)t * 64;
#pragma unroll
    for (int u = 0; u < 4; u++) {
        uint4 h4, l4;
        split8(vals + u * 8, h4, l4);
        uint32_t off = rbase + (uint32_t)((u ^ sw) << 4);
        *(uint4*)((uint8_t*)hi + plane + off) = h4;
        *(uint4*)((uint8_t*)lo + plane + off) = l4;
    }
}

// ---------------------------------------------------------------------------
// bulk-fed mma.sync grouped GEMM with producer/consumer mbarrier dataflow.
// D[128x256] += A * B^T, bf16 hi/lo 3-pass. 512 threads (16 warps, 4Mx4N).
// full[s]: tx-tracked load completion; empty[s]: 16 per-warp read-done arrivals.
// Producer duty distributed: warp w (w<4) owns stage w, reissues on chunks
// with j&3==w — straggler coupling paid once per 4 chunks per warp.
// ---------------------------------------------------------------------------
template<int KTOT, int KSLICES, bool IS_G1>
__global__ __launch_bounds__(512, 1) void gemm_mma(float* __restrict__ out) {
    constexpr int KCA = KTOT / 32;
    constexpr int KC  = (KTOT / KSLICES) / TK;
    constexpr int NB  = (IS_G1 ? HH : DD) / TN;
    int zz = blockIdx.z;
    int e = zz & (EE - 1);
    int slice = zz >> 3;
    int kc0 = slice * KC;
    int cnt = g_cnt[e];
    int m0  = blockIdx.y * TM;
    if (m0 >= cnt) return;
    int mb  = blockIdx.y;
    int nb  = blockIdx.x;
    int n0  = nb * TN;

    extern __shared__ char smem[];
    uint32_t sb = smem_u32(smem);
    uint32_t fullb  = sb + 4 * STAGE_BYTES;        // 4 x 8B
    uint32_t emptyb = fullb + 32;                  // 4 x 8B

    const uint8_t *pAh, *pAl, *pBh, *pBl;
    {
        size_t ap = (((size_t)e * 64 + mb) * KCA) * 8192;
        size_t bp = (((size_t)e * NB + nb) * KCA) * 16384;
        if (IS_G1) {
            pAh = (const uint8_t*)g_xg_hi + ap;  pAl = (const uint8_t*)g_xg_lo + ap;
            pBh = (const uint8_t*)g_w1t_hi + bp; pBl = (const uint8_t*)g_w1t_lo + bp;
        } else {
            pAh = (const uint8_t*)g_h_hi + ap;   pAl = (const uint8_t*)g_h_lo + ap;
            pBh = (const uint8_t*)g_w2t_hi + bp; pBl = (const uint8_t*)g_w2t_lo + bp;
        }
    }

    int tid = threadIdx.x;
    int wid = tid >> 5, lane = tid & 31;

    if (tid == 0) {
#pragma unroll
        for (int s = 0; s < 4; s++) {
            MBAR_INIT(fullb + s * 8, 1);
            MBAR_INIT(emptyb + s * 8, 16);
        }
    }
    __syncthreads();

    auto issue = [&](int j) {
        int s = j & 3;
        uint32_t st = sb + (uint32_t)s * STAGE_BYTES;
        uint32_t mb_s = fullb + s * 8;
        size_t kc = (size_t)(kc0 + j);
        MBAR_EXPECT_TX(mb_s, STAGE_BYTES);
        bulk_g2s(st,        pAh + kc * 8192, 8192, mb_s);
        bulk_g2s(st + A_LO, pAl + kc * 8192, 8192, mb_s);
        bulk_g2s(st + B_HI, pBh + kc * 16384, 16384, mb_s);
        bulk_g2s(st + B_LO, pBl + kc * 16384, 16384, mb_s);
    };
    // initial fills: warp w issues stage w (w < 4)
    if (wid < 4 && lane == 0 && wid < KC) issue(wid);

    // ---- warp / lane geometry ----
    int wm = wid & 3;
    int wn = wid >> 2;
    int li = lane >> 3;
    int lr = lane & 7;
    int kadd = li >> 1;
    int rsel = (li & 1) * 8 + lr;

    uint32_t abase[2]; int asw[2];
#pragma unroll
    for (int mt = 0; mt < 2; mt++) {
        int m = wm * 32 + mt * 16 + rsel;
        abase[mt] = (uint32_t)m * 64;
        asw[mt] = (m >> 1) & 3;
    }
    uint32_t bbase[4]; int bsw[4];
#pragma unroll
    for (int p = 0; p < 4; p++) {
        int n = wn * 64 + p * 16 + rsel;
        bbase[p] = (uint32_t)n * 64;
        bsw[p] = (n >> 1) & 3;
    }

    float acc[2][8][4];
#pragma unroll
    for (int a = 0; a < 2; a++)
#pragma unroll
        for (int b = 0; b < 8; b++)
#pragma unroll
            for (int c = 0; c < 4; c++) acc[a][b][c] = 0.f;

    for (int j = 0; j < KC; j++) {
        int s = j & 3;
        uint32_t ph = (j >> 2) & 1;
        MBAR_WAIT(fullb + s * 8, ph);
        uint32_t st = sb + (uint32_t)s * STAGE_BYTES;
#pragma unroll
        for (int kqi = 0; kqi < 2; kqi++) {
            int kq = kqi * 2;
            uint32_t ahi[2][4], alo[2][4];
#pragma unroll
            for (int mt = 0; mt < 2; mt++) {
                uint32_t off = abase[mt] + (uint32_t)((((kq + kadd) ^ asw[mt])) << 4);
                ldsm4(ahi[mt], st + off);
                ldsm4(alo[mt], st + A_LO + off);
            }
#pragma unroll
            for (int p = 0; p < 4; p++) {
                uint32_t bh[4], bl[4];
                uint32_t off = bbase[p] + (uint32_t)((((kq + kadd) ^ bsw[p])) << 4);
                ldsm4(bh, st + B_HI + off);
                ldsm4(bl, st + B_LO + off);
                // after the warp's LAST smem read of this stage, release it
                if (kqi == 1 && p == 3 && lane == 0) MBAR_ARRIVE_REL(emptyb + s * 8);
#pragma unroll
                for (int mt = 0; mt < 2; mt++) {
#pragma unroll
                    for (int sgl = 0; sgl < 2; sgl++) {
                        float* c = acc[mt][p * 2 + sgl];
                        mma16816(c, ahi[mt], bh[sgl], bh[2 + sgl]);
                        mma16816(c, ahi[mt], bl[sgl], bl[2 + sgl]);
                        mma16816(c, alo[mt], bh[sgl], bh[2 + sgl]);
                    }
                }
            }
        }
        // distributed producer: warp (j&3) reissues stage s for chunk j+4
        if (wid == s && lane == 0 && j + 4 < KC) {
            MBAR_WAIT(emptyb + s * 8, ph);
            issue(j + 4);
        }
    }

    // ---- epilogue ----
    int r4 = lane >> 2, cpair = (lane & 3) * 2;
    if (IS_G1) {
        size_t planeH0 = (((size_t)e * 64 + mb) * 64) * 8192;
#pragma unroll
        for (int mt = 0; mt < 2; mt++) {
#pragma unroll
            for (int q = 0; q < 8; q++) {
                int kcH = (n0 >> 5) + wn * 2 + (q >> 2);
                int u = q & 3;
#pragma unroll
                for (int half = 0; half < 2; half++) {
                    int lm = wm * 32 + mt * 16 + r4 + half * 8;
                    float v0 = acc[mt][q][half * 2 + 0];
                    float v1 = acc[mt][q][half * 2 + 1];
                    v0 = fmaxf(v0, 0.f); v0 *= v0;
                    v1 = fmaxf(v1, 0.f); v1 *= v1;
                    __nv_bfloat16 h0 = __float2bfloat16(v0), h1 = __float2bfloat16(v1);
                    uint32_t hw = (uint32_t)__bfloat16_as_ushort(h0) |
                                  ((uint32_t)__bfloat16_as_ushort(h1) << 16);
                    uint32_t lw = pack2(v0 - __bfloat162float(h0), v1 - __bfloat162float(h1));
                    size_t off = planeH0 + (size_t)kcH * 8192 +
                                 (uint32_t)(lm * 64 + ((u ^ ((lm >> 1) & 3)) << 4) + cpair * 2);
                    *(uint32_t*)((uint8_t*)g_h_hi + off) = hw;
                    *(uint32_t*)((uint8_t*)g_h_lo + off) = lw;
                }
            }
        }
    } else {
#pragma unroll
        for (int mt = 0; mt < 2; mt++) {
            int gm = m0 + wm * 32 + mt * 16;
            int   tokh[2];
            float gth[2];
#pragma unroll
            for (int half = 0; half < 2; half++) {
                int slot = gm + r4 + half * 8;
                bool ok = slot < cnt;
                tokh[half] = ok ? g_tok[e * NN + slot] : -1;
                gth[half]  = ok ? g_gate[e * NN + slot] : 0.f;
            }
#pragma unroll
            for (int q = 0; q < 8; q++) {
                int gn = n0 + wn * 64 + q * 8 + cpair;
#pragma unroll
                for (int half = 0; half < 2; half++) {
                    if (tokh[half] >= 0) {
                        float* orow = out + (size_t)tokh[half] * DD + gn;
                        atomicAdd(orow,     gth[half] * acc[mt][q][half * 2 + 0]);
                        atomicAdd(orow + 1, gth[half] * acc[mt][q][half * 2 + 1]);
                    }
                }
            }
        }
    }
}

// ---------------------------------------------------------------------------
extern "C" void kernel_launch(void* const* d_in, const int* in_sizes, int n_in,
                              void* d_out, int out_size) {
    const float* x  = (const float*)d_in[0];   // (B,T,D)
    const float* rw = (const float*)d_in[1];   // (E,D)
    const float* w1 = (const float*)d_in[2];   // (E,D,H)
    const float* w2 = (const float*)d_in[3];   // (E,H,D)
    float* out = (float*)d_out;                // (B,T,D) fp32

    cudaFuncSetAttribute(gemm_mma<DD, 1, true>,  cudaFuncAttributeMaxDynamicSharedMemorySize, SMEM_BYTES);
    cudaFuncSetAttribute(gemm_mma<HH, 2, false>, cudaFuncAttributeMaxDynamicSharedMemorySize, SMEM_BYTES);

    int zblocks = out_size / (4 * 256);
    zero_kernel<<<zblocks, 256>>>((float4*)out);
    router_kernel<<<NN, 256>>>(x, rw);
    wsplit_kernel<DD, HH, 0><<<dim3(DD / 32, HH / 256, EE), 256>>>(w1);
    wsplit_kernel<HH, DD, 1><<<dim3(HH / 32, DD / 256, EE), 256>>>(w2);
    gather_kernel<<<dim3(NN, EE), 128>>>(x);
    gemm_mma<DD, 1, true><<<dim3(HH / TN, NN / TM, EE), 512, SMEM_BYTES>>>(nullptr);
    gemm_mma<HH, 2, false><<<dim3(DD / TN, NN / TM, EE * 2), 512, SMEM_BYTES>>>(out);
}

// round 11
// speedup vs baseline: 2.8702x; 1.0993x over previous
#include <cuda_runtime.h>
#include <cuda_bf16.h>
#include <cstdint>

// ---------------- problem constants ----------------
#define DD   1024
#define EE   8
#define HH   2048
#define NN   8192   // B*T tokens

// GEMM tile config: CTA 128x128, 8 warps (4M x 2N), warp tile 32x64, K-chunk 32
#define TM   128
#define TN   128
#define TK   32
#define A_LO 8192
#define B_HI 16384
#define B_LO 24576
#define STAGE_BYTES 32768            // Ahi8K + Alo8K + Bhi8K + Blo8K
#define NSTAGE 3
#define SMEM_BYTES  (NSTAGE*STAGE_BYTES + 64)   // 3 stages + full/empty mbarriers

// Tiled-plane geometry:
//  A planes: per (e, mblock, kchunk): 8192B, 128 rows x 64B, swizzled
//  B planes: per (e, nblock128, kchunk): 8192B, 128 rows x 64B, swizzled
//  row byte: m*64 + ((u ^ ((m>>1)&3))<<4) + (k&7)*2,  u = (k>>3)&3

// ---------------- static device scratch ----------------
__device__ int   g_cnt[EE];
__device__ int   g_tok[EE * NN];
__device__ float g_gate[EE * NN];
__device__ __nv_bfloat16 g_xg_hi[(size_t)EE * NN * DD];   // [e][mb<64][kc<32][8KB]
__device__ __nv_bfloat16 g_xg_lo[(size_t)EE * NN * DD];
__device__ __nv_bfloat16 g_h_hi [(size_t)EE * NN * HH];   // [e][mb<64][kc<64][8KB]
__device__ __nv_bfloat16 g_h_lo [(size_t)EE * NN * HH];
__device__ __nv_bfloat16 g_w1t_hi[(size_t)EE * DD * HH];  // [e][nb<16][kc<32][8KB]
__device__ __nv_bfloat16 g_w1t_lo[(size_t)EE * DD * HH];
__device__ __nv_bfloat16 g_w2t_hi[(size_t)EE * HH * DD];  // [e][nb<8][kc<64][8KB]
__device__ __nv_bfloat16 g_w2t_lo[(size_t)EE * HH * DD];

// ---------------- helpers ----------------
__device__ __forceinline__ uint32_t smem_u32(const void* p) {
    uint32_t a;
    asm("{ .reg .u64 t; cvta.to.shared.u64 t, %1; cvt.u32.u64 %0, t; }" : "=r"(a) : "l"(p));
    return a;
}
__device__ __forceinline__ void ldsm4(uint32_t* r, uint32_t a) {
    asm volatile("ldmatrix.sync.aligned.m8n8.x4.shared.b16 {%0,%1,%2,%3}, [%4];"
                 : "=r"(r[0]), "=r"(r[1]), "=r"(r[2]), "=r"(r[3]) : "r"(a));
}
__device__ __forceinline__ void mma16816(float* c, const uint32_t* a, uint32_t b0, uint32_t b1) {
    asm volatile("mma.sync.aligned.m16n8k16.row.col.f32.bf16.bf16.f32 "
                 "{%0,%1,%2,%3}, {%4,%5,%6,%7}, {%8,%9}, {%0,%1,%2,%3};"
                 : "+f"(c[0]), "+f"(c[1]), "+f"(c[2]), "+f"(c[3])
                 : "r"(a[0]), "r"(a[1]), "r"(a[2]), "r"(a[3]), "r"(b0), "r"(b1));
}
__device__ __forceinline__ uint32_t pack2(float a, float b) {
    __nv_bfloat16 h0 = __float2bfloat16(a), h1 = __float2bfloat16(b);
    return (uint32_t)__bfloat16_as_ushort(h0) | ((uint32_t)__bfloat16_as_ushort(h1) << 16);
}
#define MBAR_INIT(a, c) asm volatile("mbarrier.init.shared.b64 [%0], %1;" :: "r"(a), "r"((uint32_t)(c)) : "memory")
#define MBAR_EXPECT_TX(a, tx) asm volatile("mbarrier.arrive.expect_tx.shared.b64 _, [%0], %1;" :: "r"(a), "r"((uint32_t)(tx)) : "memory")
#define MBAR_ARRIVE_REL(a) asm volatile("mbarrier.arrive.release.cta.shared::cta.b64 _, [%0];" :: "r"(a) : "memory")
#define MBAR_WAIT(a, ph) do { \
    uint32_t _m = (a); uint32_t _p = (uint32_t)(ph); uint32_t _d; \
    asm volatile("{\n\t.reg .pred p;\n\tmbarrier.try_wait.parity.acquire.cta.shared::cta.b64 p, [%1], %2;\n\tselp.b32 %0,1,0,p;\n\t}" \
        : "=r"(_d) : "r"(_m), "r"(_p) : "memory"); \
    if (!_d) { \
        asm volatile("{\n\t.reg .pred P1;\n\tWL_%=:\n\tmbarrier.try_wait.parity.acquire.cta.shared::cta.b64 P1, [%0], %1, 0x989680;\n\t@P1 bra.uni WD_%=;\n\tbra.uni WL_%=;\n\tWD_%=:\n\t}" \
            :: "r"(_m), "r"(_p) : "memory"); \
    } } while (0)
__device__ __forceinline__ void bulk_g2s(uint32_t dst, const void* src, uint32_t bytes, uint32_t mbar) {
    asm volatile("cp.async.bulk.shared::cta.global.mbarrier::complete_tx::bytes [%0], [%1], %2, [%3];"
                 :: "r"(dst), "l"(src), "r"(bytes), "r"(mbar) : "memory");
}

// pack 8 floats -> 16B hi plane + 16B lo plane
__device__ __forceinline__ void split8(const float* v, uint4& hi, uint4& lo) {
    uint32_t h[4], l[4];
#pragma unroll
    for (int i = 0; i < 4; i++) {
        __nv_bfloat16 a = __float2bfloat16(v[2*i]), b = __float2bfloat16(v[2*i+1]);
        h[i] = (uint32_t)__bfloat16_as_ushort(a) | ((uint32_t)__bfloat16_as_ushort(b) << 16);
        l[i] = pack2(v[2*i] - __bfloat162float(a), v[2*i+1] - __bfloat162float(b));
    }
    hi = make_uint4(h[0], h[1], h[2], h[3]);
    lo = make_uint4(l[0], l[1], l[2], l[3]);
}

// ---------------------------------------------------------------------------
// Kernel 0: zero output + reset counters
// ---------------------------------------------------------------------------
__global__ void zero_kernel(float4* __restrict__ out) {
    int i = blockIdx.x * blockDim.x + threadIdx.x;
    out[i] = make_float4(0.f, 0.f, 0.f, 0.f);
    if (blockIdx.x == 0 && threadIdx.x < EE) g_cnt[threadIdx.x] = 0;
}

// ---------------------------------------------------------------------------
// Kernel 1: router (fp32, validated)
// ---------------------------------------------------------------------------
__global__ __launch_bounds__(256) void router_kernel(const float* __restrict__ x,
                                                     const float* __restrict__ rw) {
    int n = blockIdx.x, tid = threadIdx.x;
    const float* xr = x + (size_t)n * DD;
    float acc[EE];
#pragma unroll
    for (int e = 0; e < EE; e++) acc[e] = 0.f;
    for (int i = tid; i < DD; i += 256) {
        float xv = xr[i];
#pragma unroll
        for (int e = 0; e < EE; e++) acc[e] += xv * rw[e * DD + i];
    }
#pragma unroll
    for (int e = 0; e < EE; e++)
#pragma unroll
        for (int o = 16; o > 0; o >>= 1) acc[e] += __shfl_down_sync(0xffffffffu, acc[e], o);

    __shared__ float sm[8][EE];
    int warp = tid >> 5, lane = tid & 31;
    if (lane == 0)
#pragma unroll
        for (int e = 0; e < EE; e++) sm[warp][e] = acc[e];
    __syncthreads();

    if (tid == 0) {
        float logits[EE];
#pragma unroll
        for (int e = 0; e < EE; e++) {
            float s = 0.f;
#pragma unroll
            for (int w = 0; w < 8; w++) s += sm[w][e];
            logits[e] = s;
        }
        int i0 = 0; float v0 = logits[0];
#pragma unroll
        for (int e = 1; e < EE; e++) if (logits[e] > v0) { v0 = logits[e]; i0 = e; }
        int i1 = 0; float v1 = -3.0e38f;
#pragma unroll
        for (int e = 0; e < EE; e++) if (e != i0 && logits[e] > v1) { v1 = logits[e]; i1 = e; }
        float ex = __expf(v1 - v0);
        float g0 = 1.f / (1.f + ex);
        float g1 = ex * g0;
        int p0 = atomicAdd(&g_cnt[i0], 1);
        g_tok[i0 * NN + p0] = n;  g_gate[i0 * NN + p0] = g0;
        int p1 = atomicAdd(&g_cnt[i1], 1);
        g_tok[i1 * NN + p1] = n;  g_gate[i1 * NN + p1] = g1;
    }
}

// ---------------------------------------------------------------------------
// Kernel 2: gather tokens, split hi/lo into swizzled tiled A planes
// ---------------------------------------------------------------------------
__global__ __launch_bounds__(128) void gather_kernel(const float* __restrict__ x) {
    int e = blockIdx.y, slot = blockIdx.x;
    int cnt = g_cnt[e];
    int pad = (cnt + 127) & ~127;  if (pad > NN) pad = NN;
    if (slot >= pad) return;
    int mb = slot >> 7, m = slot & 127;
    int t = threadIdx.x;
    int kc = t >> 2, u = t & 3;
    size_t plane = (((size_t)e * 64 + mb) * 32 + kc) * 8192;
    uint32_t off = (uint32_t)m * 64 + (uint32_t)((u ^ ((m >> 1) & 3)) << 4);
    uint8_t* dh = (uint8_t*)g_xg_hi + plane + off;
    uint8_t* dl = (uint8_t*)g_xg_lo + plane + off;
    if (slot < cnt) {
        int tok = g_tok[e * NN + slot];
        const float4* xs = (const float4*)(x + (size_t)tok * DD + t * 8);
        float v[8];
        float4 a = xs[0], b = xs[1];
        v[0]=a.x; v[1]=a.y; v[2]=a.z; v[3]=a.w; v[4]=b.x; v[5]=b.y; v[6]=b.z; v[7]=b.w;
        uint4 hi, lo;
        split8(v, hi, lo);
        *(uint4*)dh = hi;
        *(uint4*)dl = lo;
    } else {
        uint4 z = make_uint4(0,0,0,0);
        *(uint4*)dh = z;
        *(uint4*)dl = z;
    }
}

// ---------------------------------------------------------------------------
// Kernels 3/4: weights -> transposed, split, swizzled tiled B planes (8KB, 128 rows)
// w [E][R][C] fp32 -> planes [E][nb=C/128][kc=R/32][8192B]
// grid (R/32, C/256, E), 256 threads: thread t -> nb = by*2 + (t>>7), row = t&127
// ---------------------------------------------------------------------------
template<int R, int C, int WHICH>
__global__ __launch_bounds__(256) void wsplit_kernel(const float* __restrict__ w) {
    int kc = blockIdx.x, nb2 = blockIdx.y, e = blockIdx.z;
    const float* src = w + (size_t)e * R * C;
    int t = threadIdx.x;
    int n = nb2 * 256 + t;
    float vals[32];
#pragma unroll
    for (int j = 0; j < 32; j++)
        vals[j] = src[(size_t)(kc * 32 + j) * C + n];
    __nv_bfloat16* hi = (WHICH == 0) ? g_w1t_hi : g_w2t_hi;
    __nv_bfloat16* lo = (WHICH == 0) ? g_w1t_lo : g_w2t_lo;
    int nb = nb2 * 2 + (t >> 7);
    int m  = t & 127;
    size_t plane = (((size_t)e * (C / 128) + nb) * (R / 32) + kc) * 8192;
    int sw = (m >> 1) & 3;
    uint32_t rbase = (uint32_t)m * 64;
#pragma unroll
    for (int u = 0; u < 4; u++) {
        uint4 h4, l4;
        split8(vals + u * 8, h4, l4);
        uint32_t off = rbase + (uint32_t)((u ^ sw) << 4);
        *(uint4*)((uint8_t*)hi + plane + off) = h4;
        *(uint4*)((uint8_t*)lo + plane + off) = l4;
    }
}

// ---------------------------------------------------------------------------
// bulk-fed mma.sync grouped GEMM, occupancy 2, 3-stage mbarrier pipeline.
// D[128x128] += A * B^T, bf16 hi/lo 3-pass. 256 threads (8 warps, 4Mx2N).
// full[s]: tx-tracked; empty[s]: 8 per-warp arrivals. Warp w<3 owns stage w.
// ---------------------------------------------------------------------------
template<int KTOT, int KSLICES, bool IS_G1>
__global__ __launch_bounds__(256, 2) void gemm_mma(float* __restrict__ out) {
    constexpr int KC  = (KTOT / KSLICES) / TK;
    constexpr int NBP = (IS_G1 ? HH : DD) / 128;   // B planes per expert
    constexpr int KCB = KTOT / 32;                 // kc dim of B plane array
    int zz = blockIdx.z;
    int e = zz & (EE - 1);
    int slice = zz >> 3;
    int kc0 = slice * KC;
    int cnt = g_cnt[e];
    int m0  = blockIdx.y * TM;
    if (m0 >= cnt) return;
    int mb  = blockIdx.y;
    int nb  = blockIdx.x;
    int n0  = nb * TN;

    extern __shared__ char smem[];
    uint32_t sb = smem_u32(smem);
    uint32_t fullb  = sb + NSTAGE * STAGE_BYTES;   // 3 x 8B
    uint32_t emptyb = fullb + 24;                  // 3 x 8B

    const uint8_t *pAh, *pAl, *pBh, *pBl;
    {
        size_t ap = (((size_t)e * 64 + mb) * (KTOT / 32)) * 8192;
        size_t bp = (((size_t)e * NBP + nb) * KCB) * 8192;
        if (IS_G1) {
            pAh = (const uint8_t*)g_xg_hi + ap;  pAl = (const uint8_t*)g_xg_lo + ap;
            pBh = (const uint8_t*)g_w1t_hi + bp; pBl = (const uint8_t*)g_w1t_lo + bp;
        } else {
            pAh = (const uint8_t*)g_h_hi + ap;   pAl = (const uint8_t*)g_h_lo + ap;
            pBh = (const uint8_t*)g_w2t_hi + bp; pBl = (const uint8_t*)g_w2t_lo + bp;
        }
    }

    int tid = threadIdx.x;
    int wid = tid >> 5, lane = tid & 31;

    if (tid == 0) {
#pragma unroll
        for (int s = 0; s < NSTAGE; s++) {
            MBAR_INIT(fullb + s * 8, 1);
            MBAR_INIT(emptyb + s * 8, 8);
        }
    }
    __syncthreads();

    auto issue = [&](int j, int s) {
        uint32_t st = sb + (uint32_t)s * STAGE_BYTES;
        uint32_t mb_s = fullb + s * 8;
        size_t kc = (size_t)(kc0 + j);
        MBAR_EXPECT_TX(mb_s, STAGE_BYTES);
        bulk_g2s(st,        pAh + kc * 8192, 8192, mb_s);
        bulk_g2s(st + A_LO, pAl + kc * 8192, 8192, mb_s);
        bulk_g2s(st + B_HI, pBh + kc * 8192, 8192, mb_s);
        bulk_g2s(st + B_LO, pBl + kc * 8192, 8192, mb_s);
    };
    // initial fills: warp w issues stage w (w < 3)
    if (wid < NSTAGE && lane == 0 && wid < KC) issue(wid, wid);

    // ---- warp / lane geometry: 4 warps M x 2 warps N, warp tile 32x64 ----
    int wm = wid & 3;
    int wn = wid >> 2;          // 0..1
    int li = lane >> 3;
    int lr = lane & 7;
    int kadd = li >> 1;
    int rsel = (li & 1) * 8 + lr;

    uint32_t abase[2]; int asw[2];
#pragma unroll
    for (int mt = 0; mt < 2; mt++) {
        int m = wm * 32 + mt * 16 + rsel;
        abase[mt] = (uint32_t)m * 64;
        asw[mt] = (m >> 1) & 3;
    }
    uint32_t bbase[4]; int bsw[4];
#pragma unroll
    for (int p = 0; p < 4; p++) {
        int n = wn * 64 + p * 16 + rsel;
        bbase[p] = (uint32_t)n * 64;
        bsw[p] = (n >> 1) & 3;
    }

    float acc[2][8][4];
#pragma unroll
    for (int a = 0; a < 2; a++)
#pragma unroll
        for (int b = 0; b < 8; b++)
#pragma unroll
            for (int c = 0; c < 4; c++) acc[a][b][c] = 0.f;

    int s = 0;
    uint32_t ph = 0;
    for (int j = 0; j < KC; j++) {
        MBAR_WAIT(fullb + s * 8, ph);
        uint32_t st = sb + (uint32_t)s * STAGE_BYTES;
#pragma unroll
        for (int kqi = 0; kqi < 2; kqi++) {
            int kq = kqi * 2;
            uint32_t ahi[2][4], alo[2][4];
#pragma unroll
            for (int mt = 0; mt < 2; mt++) {
                uint32_t off = abase[mt] + (uint32_t)((((kq + kadd) ^ asw[mt])) << 4);
                ldsm4(ahi[mt], st + off);
                ldsm4(alo[mt], st + A_LO + off);
            }
#pragma unroll
            for (int p = 0; p < 4; p++) {
                uint32_t bh[4], bl[4];
                uint32_t off = bbase[p] + (uint32_t)((((kq + kadd) ^ bsw[p])) << 4);
                ldsm4(bh, st + B_HI + off);
                ldsm4(bl, st + B_LO + off);
                // after the warp's LAST smem read of this stage, release it
                if (kqi == 1 && p == 3 && lane == 0) MBAR_ARRIVE_REL(emptyb + s * 8);
#pragma unroll
                for (int mt = 0; mt < 2; mt++) {
#pragma unroll
                    for (int sgl = 0; sgl < 2; sgl++) {
                        float* c = acc[mt][p * 2 + sgl];
                        mma16816(c, ahi[mt], bh[sgl], bh[2 + sgl]);
                        mma16816(c, ahi[mt], bl[sgl], bl[2 + sgl]);
                        mma16816(c, alo[mt], bh[sgl], bh[2 + sgl]);
                    }
                }
            }
        }
        // distributed producer: warp s reissues stage s for chunk j+3
        if (wid == s && lane == 0 && j + NSTAGE < KC) {
            MBAR_WAIT(emptyb + s * 8, ph);
            issue(j + NSTAGE, s);
        }
        if (++s == NSTAGE) { s = 0; ph ^= 1; }
    }

    // ---- epilogue ----
    int r4 = lane >> 2, cpair = (lane & 3) * 2;
    if (IS_G1) {
        size_t planeH0 = (((size_t)e * 64 + mb) * 64) * 8192;
#pragma unroll
        for (int mt = 0; mt < 2; mt++) {
#pragma unroll
            for (int q = 0; q < 8; q++) {
                int kcH = (n0 >> 5) + wn * 2 + (q >> 2);
                int u = q & 3;
#pragma unroll
                for (int half = 0; half < 2; half++) {
                    int lm = wm * 32 + mt * 16 + r4 + half * 8;
                    float v0 = acc[mt][q][half * 2 + 0];
                    float v1 = acc[mt][q][half * 2 + 1];
                    v0 = fmaxf(v0, 0.f); v0 *= v0;
                    v1 = fmaxf(v1, 0.f); v1 *= v1;
                    __nv_bfloat16 h0 = __float2bfloat16(v0), h1 = __float2bfloat16(v1);
                    uint32_t hw = (uint32_t)__bfloat16_as_ushort(h0) |
                                  ((uint32_t)__bfloat16_as_ushort(h1) << 16);
                    uint32_t lw = pack2(v0 - __bfloat162float(h0), v1 - __bfloat162float(h1));
                    size_t off = planeH0 + (size_t)kcH * 8192 +
                                 (uint32_t)(lm * 64 + ((u ^ ((lm >> 1) & 3)) << 4) + cpair * 2);
                    *(uint32_t*)((uint8_t*)g_h_hi + off) = hw;
                    *(uint32_t*)((uint8_t*)g_h_lo + off) = lw;
                }
            }
        }
    } else {
#pragma unroll
        for (int mt = 0; mt < 2; mt++) {
            int gm = m0 + wm * 32 + mt * 16;
            int   tokh[2];
            float gth[2];
#pragma unroll
            for (int half = 0; half < 2; half++) {
                int slot = gm + r4 + half * 8;
                bool ok = slot < cnt;
                tokh[half] = ok ? g_tok[e * NN + slot] : -1;
                gth[half]  = ok ? g_gate[e * NN + slot] : 0.f;
            }
#pragma unroll
            for (int q = 0; q < 8; q++) {
                int gn = n0 + wn * 64 + q * 8 + cpair;
#pragma unroll
                for (int half = 0; half < 2; half++) {
                    if (tokh[half] >= 0) {
                        float* orow = out + (size_t)tokh[half] * DD + gn;
                        atomicAdd(orow,     gth[half] * acc[mt][q][half * 2 + 0]);
                        atomicAdd(orow + 1, gth[half] * acc[mt][q][half * 2 + 1]);
                    }
                }
            }
        }
    }
}

// ---------------------------------------------------------------------------
extern "C" void kernel_launch(void* const* d_in, const int* in_sizes, int n_in,
                              void* d_out, int out_size) {
    const float* x  = (const float*)d_in[0];   // (B,T,D)
    const float* rw = (const float*)d_in[1];   // (E,D)
    const float* w1 = (const float*)d_in[2];   // (E,D,H)
    const float* w2 = (const float*)d_in[3];   // (E,H,D)
    float* out = (float*)d_out;                // (B,T,D) fp32

    cudaFuncSetAttribute(gemm_mma<DD, 1, true>,  cudaFuncAttributeMaxDynamicSharedMemorySize, SMEM_BYTES);
    cudaFuncSetAttribute(gemm_mma<HH, 2, false>, cudaFuncAttributeMaxDynamicSharedMemorySize, SMEM_BYTES);

    int zblocks = out_size / (4 * 256);
    zero_kernel<<<zblocks, 256>>>((float4*)out);
    router_kernel<<<NN, 256>>>(x, rw);
    wsplit_kernel<DD, HH, 0><<<dim3(DD / 32, HH / 256, EE), 256>>>(w1);
    wsplit_kernel<HH, DD, 1><<<dim3(HH / 32, DD / 256, EE), 256>>>(w2);
    gather_kernel<<<dim3(NN, EE), 128>>>(x);
    gemm_mma<DD, 1, true><<<dim3(HH / TN, NN / TM, EE), 256, SMEM_BYTES>>>(nullptr);
    gemm_mma<HH, 2, false><<<dim3(DD / TN, NN / TM, EE * 2), 256, SMEM_BYTES>>>(out);
}

// round 12
// speedup vs baseline: 3.3274x; 1.1593x over previous
#include <cuda_runtime.h>
#include <cuda_bf16.h>
#include <cuda_fp16.h>
#include <cstdint>

// ---------------- problem constants ----------------
#define DD   1024
#define EE   8
#define HH   2048
#define NN   8192   // B*T tokens

// GEMM tile config: CTA 128x128, 8 warps (4M x 2N), warp tile 32x64, K-chunk 32
#define TM   128
#define TN   128
#define TK   32
// G1 stage: Ahi8K + Alo8K + Bhi8K + Blo8K (bf16 3-pass)
#define A_LO 8192
#define B_HI 16384
#define B_LO 24576
#define STAGE_BYTES 32768
#define NSTAGE 3
#define SMEM_BYTES  (NSTAGE*STAGE_BYTES + 64)
// G2 stage: Ahi8K + Alo8K + B8K (fp16 2-pass)
#define B2_OFF 16384
#define STAGE2_BYTES 24576
#define NSTAGE2 4
#define SMEM2_BYTES (NSTAGE2*STAGE2_BYTES + 64)

// Tiled-plane geometry (all planes 8192B = 128 rows x 64B, swizzled):
//  row byte: m*64 + ((u ^ ((m>>1)&3))<<4) + (k&7)*2,  u = (k>>3)&3

// ---------------- static device scratch ----------------
__device__ int   g_cnt[EE];
__device__ int   g_tok[EE * NN];
__device__ float g_gate[EE * NN];
__device__ __nv_bfloat16 g_xg_hi[(size_t)EE * NN * DD];   // [e][mb<64][kc<32][8KB]
__device__ __nv_bfloat16 g_xg_lo[(size_t)EE * NN * DD];
__device__ __half        g_h_hi [(size_t)EE * NN * HH];   // [e][mb<64][kc<64][8KB] fp16
__device__ __half        g_h_lo [(size_t)EE * NN * HH];
__device__ __nv_bfloat16 g_w1t_hi[(size_t)EE * DD * HH];  // [e][nb<16][kc<32][8KB]
__device__ __nv_bfloat16 g_w1t_lo[(size_t)EE * DD * HH];
__device__ __half        g_w2t  [(size_t)EE * HH * DD];   // [e][nb<8][kc<64][8KB] fp16 single

// ---------------- helpers ----------------
__device__ __forceinline__ uint32_t smem_u32(const void* p) {
    uint32_t a;
    asm("{ .reg .u64 t; cvta.to.shared.u64 t, %1; cvt.u32.u64 %0, t; }" : "=r"(a) : "l"(p));
    return a;
}
__device__ __forceinline__ void ldsm4(uint32_t* r, uint32_t a) {
    asm volatile("ldmatrix.sync.aligned.m8n8.x4.shared.b16 {%0,%1,%2,%3}, [%4];"
                 : "=r"(r[0]), "=r"(r[1]), "=r"(r[2]), "=r"(r[3]) : "r"(a));
}
__device__ __forceinline__ void mma_bf16(float* c, const uint32_t* a, uint32_t b0, uint32_t b1) {
    asm volatile("mma.sync.aligned.m16n8k16.row.col.f32.bf16.bf16.f32 "
                 "{%0,%1,%2,%3}, {%4,%5,%6,%7}, {%8,%9}, {%0,%1,%2,%3};"
                 : "+f"(c[0]), "+f"(c[1]), "+f"(c[2]), "+f"(c[3])
                 : "r"(a[0]), "r"(a[1]), "r"(a[2]), "r"(a[3]), "r"(b0), "r"(b1));
}
__device__ __forceinline__ void mma_f16(float* c, const uint32_t* a, uint32_t b0, uint32_t b1) {
    asm volatile("mma.sync.aligned.m16n8k16.row.col.f32.f16.f16.f32 "
                 "{%0,%1,%2,%3}, {%4,%5,%6,%7}, {%8,%9}, {%0,%1,%2,%3};"
                 : "+f"(c[0]), "+f"(c[1]), "+f"(c[2]), "+f"(c[3])
                 : "r"(a[0]), "r"(a[1]), "r"(a[2]), "r"(a[3]), "r"(b0), "r"(b1));
}
__device__ __forceinline__ uint32_t pack2(float a, float b) {    // bf16 pair
    __nv_bfloat16 h0 = __float2bfloat16(a), h1 = __float2bfloat16(b);
    return (uint32_t)__bfloat16_as_ushort(h0) | ((uint32_t)__bfloat16_as_ushort(h1) << 16);
}
__device__ __forceinline__ uint32_t pack2h(float a, float b) {   // fp16 pair
    __half h0 = __float2half_rn(a), h1 = __float2half_rn(b);
    return (uint32_t)__half_as_ushort(h0) | ((uint32_t)__half_as_ushort(h1) << 16);
}
#define MBAR_INIT(a, c) asm volatile("mbarrier.init.shared.b64 [%0], %1;" :: "r"(a), "r"((uint32_t)(c)) : "memory")
#define MBAR_EXPECT_TX(a, tx) asm volatile("mbarrier.arrive.expect_tx.shared.b64 _, [%0], %1;" :: "r"(a), "r"((uint32_t)(tx)) : "memory")
#define MBAR_ARRIVE_REL(a) asm volatile("mbarrier.arrive.release.cta.shared::cta.b64 _, [%0];" :: "r"(a) : "memory")
#define MBAR_WAIT(a, ph) do { \
    uint32_t _m = (a); uint32_t _p = (uint32_t)(ph); uint32_t _d; \
    asm volatile("{\n\t.reg .pred p;\n\tmbarrier.try_wait.parity.acquire.cta.shared::cta.b64 p, [%1], %2;\n\tselp.b32 %0,1,0,p;\n\t}" \
        : "=r"(_d) : "r"(_m), "r"(_p) : "memory"); \
    if (!_d) { \
        asm volatile("{\n\t.reg .pred P1;\n\tWL_%=:\n\tmbarrier.try_wait.parity.acquire.cta.shared::cta.b64 P1, [%0], %1, 0x989680;\n\t@P1 bra.uni WD_%=;\n\tbra.uni WL_%=;\n\tWD_%=:\n\t}" \
            :: "r"(_m), "r"(_p) : "memory"); \
    } } while (0)
__device__ __forceinline__ void bulk_g2s(uint32_t dst, const void* src, uint32_t bytes, uint32_t mbar) {
    asm volatile("cp.async.bulk.shared::cta.global.mbarrier::complete_tx::bytes [%0], [%1], %2, [%3];"
                 :: "r"(dst), "l"(src), "r"(bytes), "r"(mbar) : "memory");
}

// pack 8 floats -> 16B bf16 hi plane + 16B bf16 lo plane
__device__ __forceinline__ void split8(const float* v, uint4& hi, uint4& lo) {
    uint32_t h[4], l[4];
#pragma unroll
    for (int i = 0; i < 4; i++) {
        __nv_bfloat16 a = __float2bfloat16(v[2*i]), b = __float2bfloat16(v[2*i+1]);
        h[i] = (uint32_t)__bfloat16_as_ushort(a) | ((uint32_t)__bfloat16_as_ushort(b) << 16);
        l[i] = pack2(v[2*i] - __bfloat162float(a), v[2*i+1] - __bfloat162float(b));
    }
    hi = make_uint4(h[0], h[1], h[2], h[3]);
    lo = make_uint4(l[0], l[1], l[2], l[3]);
}

// ---------------------------------------------------------------------------
// Kernel 0: zero output + reset counters
// ---------------------------------------------------------------------------
__global__ void zero_kernel(float4* __restrict__ out) {
    int i = blockIdx.x * blockDim.x + threadIdx.x;
    out[i] = make_float4(0.f, 0.f, 0.f, 0.f);
    if (blockIdx.x == 0 && threadIdx.x < EE) g_cnt[threadIdx.x] = 0;
}

// ---------------------------------------------------------------------------
// Kernel 1: router (fp32, validated)
// ---------------------------------------------------------------------------
__global__ __launch_bounds__(256) void router_kernel(const float* __restrict__ x,
                                                     const float* __restrict__ rw) {
    int n = blockIdx.x, tid = threadIdx.x;
    const float* xr = x + (size_t)n * DD;
    float acc[EE];
#pragma unroll
    for (int e = 0; e < EE; e++) acc[e] = 0.f;
    for (int i = tid; i < DD; i += 256) {
        float xv = xr[i];
#pragma unroll
        for (int e = 0; e < EE; e++) acc[e] += xv * rw[e * DD + i];
    }
#pragma unroll
    for (int e = 0; e < EE; e++)
#pragma unroll
        for (int o = 16; o > 0; o >>= 1) acc[e] += __shfl_down_sync(0xffffffffu, acc[e], o);

    __shared__ float sm[8][EE];
    int warp = tid >> 5, lane = tid & 31;
    if (lane == 0)
#pragma unroll
        for (int e = 0; e < EE; e++) sm[warp][e] = acc[e];
    __syncthreads();

    if (tid == 0) {
        float logits[EE];
#pragma unroll
        for (int e = 0; e < EE; e++) {
            float s = 0.f;
#pragma unroll
            for (int w = 0; w < 8; w++) s += sm[w][e];
            logits[e] = s;
        }
        int i0 = 0; float v0 = logits[0];
#pragma unroll
        for (int e = 1; e < EE; e++) if (logits[e] > v0) { v0 = logits[e]; i0 = e; }
        int i1 = 0; float v1 = -3.0e38f;
#pragma unroll
        for (int e = 0; e < EE; e++) if (e != i0 && logits[e] > v1) { v1 = logits[e]; i1 = e; }
        float ex = __expf(v1 - v0);
        float g0 = 1.f / (1.f + ex);
        float g1 = ex * g0;
        int p0 = atomicAdd(&g_cnt[i0], 1);
        g_tok[i0 * NN + p0] = n;  g_gate[i0 * NN + p0] = g0;
        int p1 = atomicAdd(&g_cnt[i1], 1);
        g_tok[i1 * NN + p1] = n;  g_gate[i1 * NN + p1] = g1;
    }
}

// ---------------------------------------------------------------------------
// Kernel 2: gather tokens, split bf16 hi/lo into swizzled tiled A planes
// ---------------------------------------------------------------------------
__global__ __launch_bounds__(128) void gather_kernel(const float* __restrict__ x) {
    int e = blockIdx.y, slot = blockIdx.x;
    int cnt = g_cnt[e];
    int pad = (cnt + 127) & ~127;  if (pad > NN) pad = NN;
    if (slot >= pad) return;
    int mb = slot >> 7, m = slot & 127;
    int t = threadIdx.x;
    int kc = t >> 2, u = t & 3;
    size_t plane = (((size_t)e * 64 + mb) * 32 + kc) * 8192;
    uint32_t off = (uint32_t)m * 64 + (uint32_t)((u ^ ((m >> 1) & 3)) << 4);
    uint8_t* dh = (uint8_t*)g_xg_hi + plane + off;
    uint8_t* dl = (uint8_t*)g_xg_lo + plane + off;
    if (slot < cnt) {
        int tok = g_tok[e * NN + slot];
        const float4* xs = (const float4*)(x + (size_t)tok * DD + t * 8);
        float v[8];
        float4 a = xs[0], b = xs[1];
        v[0]=a.x; v[1]=a.y; v[2]=a.z; v[3]=a.w; v[4]=b.x; v[5]=b.y; v[6]=b.z; v[7]=b.w;
        uint4 hi, lo;
        split8(v, hi, lo);
        *(uint4*)dh = hi;
        *(uint4*)dl = lo;
    } else {
        uint4 z = make_uint4(0,0,0,0);
        *(uint4*)dh = z;
        *(uint4*)dl = z;
    }
}

// ---------------------------------------------------------------------------
// Kernels 3/4: weights -> transposed, swizzled tiled B planes (8KB, 128 rows)
// WHICH 0: w1 -> bf16 hi/lo planes.  WHICH 1: w2 -> single fp16 plane.
// grid (R/32, C/256, E), 256 threads
// ---------------------------------------------------------------------------
template<int R, int C, int WHICH>
__global__ __launch_bounds__(256) void wsplit_kernel(const float* __restrict__ w) {
    int kc = blockIdx.x, nb2 = blockIdx.y, e = blockIdx.z;
    const float* src = w + (size_t)e * R * C;
    int t = threadIdx.x;
    int n = nb2 * 256 + t;
    float vals[32];
#pragma unroll
    for (int j = 0; j < 32; j++)
        vals[j] = src[(size_t)(kc * 32 + j) * C + n];
    int nb = nb2 * 2 + (t >> 7);
    int m  = t & 127;
    size_t plane = (((size_t)e * (C / 128) + nb) * (R / 32) + kc) * 8192;
    int sw = (m >> 1) & 3;
    uint32_t rbase = (uint32_t)m * 64;
    if (WHICH == 0) {
#pragma unroll
        for (int u = 0; u < 4; u++) {
            uint4 h4, l4;
            split8(vals + u * 8, h4, l4);
            uint32_t off = rbase + (uint32_t)((u ^ sw) << 4);
            *(uint4*)((uint8_t*)g_w1t_hi + plane + off) = h4;
            *(uint4*)((uint8_t*)g_w1t_lo + plane + off) = l4;
        }
    } else {
#pragma unroll
        for (int u = 0; u < 4; u++) {
            uint4 h4;
            h4.x = pack2h(vals[u*8+0], vals[u*8+1]);
            h4.y = pack2h(vals[u*8+2], vals[u*8+3]);
            h4.z = pack2h(vals[u*8+4], vals[u*8+5]);
            h4.w = pack2h(vals[u*8+6], vals[u*8+7]);
            uint32_t off = rbase + (uint32_t)((u ^ sw) << 4);
            *(uint4*)((uint8_t*)g_w2t + plane + off) = h4;
        }
    }
}

// ---------------------------------------------------------------------------
// GEMM1: bf16 3-pass (validated). occ 2, 3-stage mbarrier pipeline.
// h = relu(x@w1)^2 written as fp16 hi/lo planes for GEMM2.
// ---------------------------------------------------------------------------
__global__ __launch_bounds__(256, 2) void gemm1_mma() {
    constexpr int KC = DD / TK;      // 32
    int e = blockIdx.z;
    int cnt = g_cnt[e];
    int m0  = blockIdx.y * TM;
    if (m0 >= cnt) return;
    int mb  = blockIdx.y;
    int nb  = blockIdx.x;
    int n0  = nb * TN;

    extern __shared__ char smem[];
    uint32_t sb = smem_u32(smem);
    uint32_t fullb  = sb + NSTAGE * STAGE_BYTES;
    uint32_t emptyb = fullb + 24;

    size_t ap = (((size_t)e * 64 + mb) * 32) * 8192;
    size_t bp = (((size_t)e * 16 + nb) * 32) * 8192;
    const uint8_t* pAh = (const uint8_t*)g_xg_hi + ap;
    const uint8_t* pAl = (const uint8_t*)g_xg_lo + ap;
    const uint8_t* pBh = (const uint8_t*)g_w1t_hi + bp;
    const uint8_t* pBl = (const uint8_t*)g_w1t_lo + bp;

    int tid = threadIdx.x;
    int wid = tid >> 5, lane = tid & 31;

    if (tid == 0) {
#pragma unroll
        for (int s = 0; s < NSTAGE; s++) {
            MBAR_INIT(fullb + s * 8, 1);
            MBAR_INIT(emptyb + s * 8, 8);
        }
    }
    __syncthreads();

    auto issue = [&](int j, int s) {
        uint32_t st = sb + (uint32_t)s * STAGE_BYTES;
        uint32_t mb_s = fullb + s * 8;
        size_t kc = (size_t)j;
        MBAR_EXPECT_TX(mb_s, STAGE_BYTES);
        bulk_g2s(st,        pAh + kc * 8192, 8192, mb_s);
        bulk_g2s(st + A_LO, pAl + kc * 8192, 8192, mb_s);
        bulk_g2s(st + B_HI, pBh + kc * 8192, 8192, mb_s);
        bulk_g2s(st + B_LO, pBl + kc * 8192, 8192, mb_s);
    };
    if (wid < NSTAGE && lane == 0) issue(wid, wid);

    int wm = wid & 3;
    int wn = wid >> 2;
    int li = lane >> 3;
    int lr = lane & 7;
    int kadd = li >> 1;
    int rsel = (li & 1) * 8 + lr;

    uint32_t abase[2]; int asw[2];
#pragma unroll
    for (int mt = 0; mt < 2; mt++) {
        int m = wm * 32 + mt * 16 + rsel;
        abase[mt] = (uint32_t)m * 64;
        asw[mt] = (m >> 1) & 3;
    }
    uint32_t bbase[4]; int bsw[4];
#pragma unroll
    for (int p = 0; p < 4; p++) {
        int n = wn * 64 + p * 16 + rsel;
        bbase[p] = (uint32_t)n * 64;
        bsw[p] = (n >> 1) & 3;
    }

    float acc[2][8][4];
#pragma unroll
    for (int a = 0; a < 2; a++)
#pragma unroll
        for (int b = 0; b < 8; b++)
#pragma unroll
            for (int c = 0; c < 4; c++) acc[a][b][c] = 0.f;

    int s = 0;
    uint32_t ph = 0;
    for (int j = 0; j < KC; j++) {
        MBAR_WAIT(fullb + s * 8, ph);
        uint32_t st = sb + (uint32_t)s * STAGE_BYTES;
#pragma unroll
        for (int kqi = 0; kqi < 2; kqi++) {
            int kq = kqi * 2;
            uint32_t ahi[2][4], alo[2][4];
#pragma unroll
            for (int mt = 0; mt < 2; mt++) {
                uint32_t off = abase[mt] + (uint32_t)((((kq + kadd) ^ asw[mt])) << 4);
                ldsm4(ahi[mt], st + off);
                ldsm4(alo[mt], st + A_LO + off);
            }
#pragma unroll
            for (int p = 0; p < 4; p++) {
                uint32_t bh[4], bl[4];
                uint32_t off = bbase[p] + (uint32_t)((((kq + kadd) ^ bsw[p])) << 4);
                ldsm4(bh, st + B_HI + off);
                ldsm4(bl, st + B_LO + off);
                if (kqi == 1 && p == 3 && lane == 0) MBAR_ARRIVE_REL(emptyb + s * 8);
#pragma unroll
                for (int mt = 0; mt < 2; mt++) {
#pragma unroll
                    for (int sgl = 0; sgl < 2; sgl++) {
                        float* c = acc[mt][p * 2 + sgl];
                        mma_bf16(c, ahi[mt], bh[sgl], bh[2 + sgl]);
                        mma_bf16(c, ahi[mt], bl[sgl], bl[2 + sgl]);
                        mma_bf16(c, alo[mt], bh[sgl], bh[2 + sgl]);
                    }
                }
            }
        }
        if (wid == s && lane == 0 && j + NSTAGE < KC) {
            MBAR_WAIT(emptyb + s * 8, ph);
            issue(j + NSTAGE, s);
        }
        if (++s == NSTAGE) { s = 0; ph ^= 1; }
    }

    // epilogue: h = relu(acc)^2 -> fp16 hi/lo planes
    int r4 = lane >> 2, cpair = (lane & 3) * 2;
    size_t planeH0 = (((size_t)e * 64 + mb) * 64) * 8192;
#pragma unroll
    for (int mt = 0; mt < 2; mt++) {
#pragma unroll
        for (int q = 0; q < 8; q++) {
            int kcH = (n0 >> 5) + wn * 2 + (q >> 2);
            int u = q & 3;
#pragma unroll
            for (int half = 0; half < 2; half++) {
                int lm = wm * 32 + mt * 16 + r4 + half * 8;
                float v0 = acc[mt][q][half * 2 + 0];
                float v1 = acc[mt][q][half * 2 + 1];
                v0 = fmaxf(v0, 0.f); v0 *= v0;
                v1 = fmaxf(v1, 0.f); v1 *= v1;
                __half h0 = __float2half_rn(v0), h1 = __float2half_rn(v1);
                uint32_t hw = (uint32_t)__half_as_ushort(h0) |
                              ((uint32_t)__half_as_ushort(h1) << 16);
                uint32_t lw = pack2h(v0 - __half2float(h0), v1 - __half2float(h1));
                size_t off = planeH0 + (size_t)kcH * 8192 +
                             (uint32_t)(lm * 64 + ((u ^ ((lm >> 1) & 3)) << 4) + cpair * 2);
                *(uint32_t*)((uint8_t*)g_h_hi + off) = hw;
                *(uint32_t*)((uint8_t*)g_h_lo + off) = lw;
            }
        }
    }
}

// ---------------------------------------------------------------------------
// GEMM2: fp16 2-pass (A = h hi/lo fp16, B = w2 fp16). occ 2, 4-stage pipeline.
// split-K 2; gate-weighted atomic scatter epilogue.
// ---------------------------------------------------------------------------
__global__ __launch_bounds__(256, 2) void gemm2_mma(float* __restrict__ out) {
    constexpr int KC = (HH / 2) / TK;   // 32 per slice
    int zz = blockIdx.z;
    int e = zz & (EE - 1);
    int slice = zz >> 3;
    int kc0 = slice * KC;
    int cnt = g_cnt[e];
    int m0  = blockIdx.y * TM;
    if (m0 >= cnt) return;
    int mb  = blockIdx.y;
    int nb  = blockIdx.x;
    int n0  = nb * TN;

    extern __shared__ char smem[];
    uint32_t sb = smem_u32(smem);
    uint32_t fullb  = sb + NSTAGE2 * STAGE2_BYTES;
    uint32_t emptyb = fullb + 32;

    size_t ap = (((size_t)e * 64 + mb) * 64) * 8192;
    size_t bp = (((size_t)e * 8 + nb) * 64) * 8192;
    const uint8_t* pAh = (const uint8_t*)g_h_hi + ap;
    const uint8_t* pAl = (const uint8_t*)g_h_lo + ap;
    const uint8_t* pB  = (const uint8_t*)g_w2t + bp;

    int tid = threadIdx.x;
    int wid = tid >> 5, lane = tid & 31;

    if (tid == 0) {
#pragma unroll
        for (int s = 0; s < NSTAGE2; s++) {
            MBAR_INIT(fullb + s * 8, 1);
            MBAR_INIT(emptyb + s * 8, 8);
        }
    }
    __syncthreads();

    auto issue = [&](int j, int s) {
        uint32_t st = sb + (uint32_t)s * STAGE2_BYTES;
        uint32_t mb_s = fullb + s * 8;
        size_t kc = (size_t)(kc0 + j);
        MBAR_EXPECT_TX(mb_s, STAGE2_BYTES);
        bulk_g2s(st,          pAh + kc * 8192, 8192, mb_s);
        bulk_g2s(st + A_LO,   pAl + kc * 8192, 8192, mb_s);
        bulk_g2s(st + B2_OFF, pB  + kc * 8192, 8192, mb_s);
    };
    if (wid < NSTAGE2 && lane == 0) issue(wid, wid);

    int wm = wid & 3;
    int wn = wid >> 2;
    int li = lane >> 3;
    int lr = lane & 7;
    int kadd = li >> 1;
    int rsel = (li & 1) * 8 + lr;

    uint32_t abase[2]; int asw[2];
#pragma unroll
    for (int mt = 0; mt < 2; mt++) {
        int m = wm * 32 + mt * 16 + rsel;
        abase[mt] = (uint32_t)m * 64;
        asw[mt] = (m >> 1) & 3;
    }
    uint32_t bbase[4]; int bsw[4];
#pragma unroll
    for (int p = 0; p < 4; p++) {
        int n = wn * 64 + p * 16 + rsel;
        bbase[p] = (uint32_t)n * 64;
        bsw[p] = (n >> 1) & 3;
    }

    float acc[2][8][4];
#pragma unroll
    for (int a = 0; a < 2; a++)
#pragma unroll
        for (int b = 0; b < 8; b++)
#pragma unroll
            for (int c = 0; c < 4; c++) acc[a][b][c] = 0.f;

    int s = 0;
    uint32_t ph = 0;
    for (int j = 0; j < KC; j++) {
        MBAR_WAIT(fullb + s * 8, ph);
        uint32_t st = sb + (uint32_t)s * STAGE2_BYTES;
#pragma unroll
        for (int kqi = 0; kqi < 2; kqi++) {
            int kq = kqi * 2;
            uint32_t ahi[2][4], alo[2][4];
#pragma unroll
            for (int mt = 0; mt < 2; mt++) {
                uint32_t off = abase[mt] + (uint32_t)((((kq + kadd) ^ asw[mt])) << 4);
                ldsm4(ahi[mt], st + off);
                ldsm4(alo[mt], st + A_LO + off);
            }
#pragma unroll
            for (int p = 0; p < 4; p++) {
                uint32_t bh[4];
                uint32_t off = bbase[p] + (uint32_t)((((kq + kadd) ^ bsw[p])) << 4);
                ldsm4(bh, st + B2_OFF + off);
                if (kqi == 1 && p == 3 && lane == 0) MBAR_ARRIVE_REL(emptyb + s * 8);
#pragma unroll
                for (int mt = 0; mt < 2; mt++) {
#pragma unroll
                    for (int sgl = 0; sgl < 2; sgl++) {
                        float* c = acc[mt][p * 2 + sgl];
                        mma_f16(c, ahi[mt], bh[sgl], bh[2 + sgl]);
                        mma_f16(c, alo[mt], bh[sgl], bh[2 + sgl]);
                    }
                }
            }
        }
        if (wid == s && lane == 0 && j + NSTAGE2 < KC) {
            MBAR_WAIT(emptyb + s * 8, ph);
            issue(j + NSTAGE2, s);
        }
        if (++s == NSTAGE2) { s = 0; ph ^= 1; }
    }

    // epilogue: gate-weighted atomic scatter
    int r4 = lane >> 2, cpair = (lane & 3) * 2;
#pragma unroll
    for (int mt = 0; mt < 2; mt++) {
        int gm = m0 + wm * 32 + mt * 16;
        int   tokh[2];
        float gth[2];
#pragma unroll
        for (int half = 0; half < 2; half++) {
            int slot = gm + r4 + half * 8;
            bool ok = slot < cnt;
            tokh[half] = ok ? g_tok[e * NN + slot] : -1;
            gth[half]  = ok ? g_gate[e * NN + slot] : 0.f;
        }
#pragma unroll
        for (int q = 0; q < 8; q++) {
            int gn = n0 + wn * 64 + q * 8 + cpair;
#pragma unroll
            for (int half = 0; half < 2; half++) {
                if (tokh[half] >= 0) {
                    float* orow = out + (size_t)tokh[half] * DD + gn;
                    atomicAdd(orow,     gth[half] * acc[mt][q][half * 2 + 0]);
                    atomicAdd(orow + 1, gth[half] * acc[mt][q][half * 2 + 1]);
                }
            }
        }
    }
}

// ---------------------------------------------------------------------------
extern "C" void kernel_launch(void* const* d_in, const int* in_sizes, int n_in,
                              void* d_out, int out_size) {
    const float* x  = (const float*)d_in[0];   // (B,T,D)
    const float* rw = (const float*)d_in[1];   // (E,D)
    const float* w1 = (const float*)d_in[2];   // (E,D,H)
    const float* w2 = (const float*)d_in[3];   // (E,H,D)
    float* out = (float*)d_out;                // (B,T,D) fp32

    cudaFuncSetAttribute(gemm1_mma, cudaFuncAttributeMaxDynamicSharedMemorySize, SMEM_BYTES);
    cudaFuncSetAttribute(gemm2_mma, cudaFuncAttributeMaxDynamicSharedMemorySize, SMEM2_BYTES);

    int zblocks = out_size / (4 * 256);
    zero_kernel<<<zblocks, 256>>>((float4*)out);
    router_kernel<<<NN, 256>>>(x, rw);
    wsplit_kernel<DD, HH, 0><<<dim3(DD / 32, HH / 256, EE), 256>>>(w1);
    wsplit_kernel<HH, DD, 1><<<dim3(HH / 32, DD / 256, EE), 256>>>(w2);
    gather_kernel<<<dim3(NN, EE), 128>>>(x);
    gemm1_mma<<<dim3(HH / TN, NN / TM, EE), 256, SMEM_BYTES>>>();
    gemm2_mma<<<dim3(DD / TN, NN / TM, EE * 2), 256, SMEM2_BYTES>>>(out);
}

// round 13
// speedup vs baseline: 4.0218x; 1.2087x over previous
#include <cuda_runtime.h>
#include <cuda_bf16.h>
#include <cuda_fp16.h>
#include <cstdint>

// ---------------- problem constants ----------------
#define DD   1024
#define EE   8
#define HH   2048
#define NN   8192   // B*T tokens

// GEMM tile config: CTA 128x128, 8 warps (4M x 2N), warp tile 32x64, K-chunk 32
#define TM   128
#define TN   128
#define TK   32
// fp16 2-pass stage: Ahi8K + Alo8K + B8K
#define A_LO 8192
#define B_OFF 16384
#define STAGE_BYTES 24576
#define NSTAGE 4
#define SMEM_BYTES (NSTAGE*STAGE_BYTES + 64)

// Tiled-plane geometry (all planes 8192B = 128 rows x 64B, swizzled):
//  row byte: m*64 + ((u ^ ((m>>1)&3))<<4) + (k&7)*2,  u = (k>>3)&3

// ---------------- static device scratch ----------------
__device__ int   g_cnt[EE];
__device__ int   g_tok[EE * NN];
__device__ float g_gate[EE * NN];
__device__ __half g_xg_hi[(size_t)EE * NN * DD];   // [e][mb<64][kc<32][8KB] fp16
__device__ __half g_xg_lo[(size_t)EE * NN * DD];
__device__ __half g_h_hi [(size_t)EE * NN * HH];   // [e][mb<64][kc<64][8KB] fp16
__device__ __half g_h_lo [(size_t)EE * NN * HH];
__device__ __half g_w1t  [(size_t)EE * DD * HH];   // [e][nb<16][kc<32][8KB] fp16 single
__device__ __half g_w2t  [(size_t)EE * HH * DD];   // [e][nb<8][kc<64][8KB] fp16 single

// ---------------- helpers ----------------
__device__ __forceinline__ uint32_t smem_u32(const void* p) {
    uint32_t a;
    asm("{ .reg .u64 t; cvta.to.shared.u64 t, %1; cvt.u32.u64 %0, t; }" : "=r"(a) : "l"(p));
    return a;
}
__device__ __forceinline__ void ldsm4(uint32_t* r, uint32_t a) {
    asm volatile("ldmatrix.sync.aligned.m8n8.x4.shared.b16 {%0,%1,%2,%3}, [%4];"
                 : "=r"(r[0]), "=r"(r[1]), "=r"(r[2]), "=r"(r[3]) : "r"(a));
}
__device__ __forceinline__ void mma_f16(float* c, const uint32_t* a, uint32_t b0, uint32_t b1) {
    asm volatile("mma.sync.aligned.m16n8k16.row.col.f32.f16.f16.f32 "
                 "{%0,%1,%2,%3}, {%4,%5,%6,%7}, {%8,%9}, {%0,%1,%2,%3};"
                 : "+f"(c[0]), "+f"(c[1]), "+f"(c[2]), "+f"(c[3])
                 : "r"(a[0]), "r"(a[1]), "r"(a[2]), "r"(a[3]), "r"(b0), "r"(b1));
}
__device__ __forceinline__ uint32_t pack2h(float a, float b) {   // fp16 pair
    __half h0 = __float2half_rn(a), h1 = __float2half_rn(b);
    return (uint32_t)__half_as_ushort(h0) | ((uint32_t)__half_as_ushort(h1) << 16);
}
#define MBAR_INIT(a, c) asm volatile("mbarrier.init.shared.b64 [%0], %1;" :: "r"(a), "r"((uint32_t)(c)) : "memory")
#define MBAR_EXPECT_TX(a, tx) asm volatile("mbarrier.arrive.expect_tx.shared.b64 _, [%0], %1;" :: "r"(a), "r"((uint32_t)(tx)) : "memory")
#define MBAR_ARRIVE_REL(a) asm volatile("mbarrier.arrive.release.cta.shared::cta.b64 _, [%0];" :: "r"(a) : "memory")
#define MBAR_WAIT(a, ph) do { \
    uint32_t _m = (a); uint32_t _p = (uint32_t)(ph); uint32_t _d; \
    asm volatile("{\n\t.reg .pred p;\n\tmbarrier.try_wait.parity.acquire.cta.shared::cta.b64 p, [%1], %2;\n\tselp.b32 %0,1,0,p;\n\t}" \
        : "=r"(_d) : "r"(_m), "r"(_p) : "memory"); \
    if (!_d) { \
        asm volatile("{\n\t.reg .pred P1;\n\tWL_%=:\n\tmbarrier.try_wait.parity.acquire.cta.shared::cta.b64 P1, [%0], %1, 0x989680;\n\t@P1 bra.uni WD_%=;\n\tbra.uni WL_%=;\n\tWD_%=:\n\t}" \
            :: "r"(_m), "r"(_p) : "memory"); \
    } } while (0)
__device__ __forceinline__ void bulk_g2s(uint32_t dst, const void* src, uint32_t bytes, uint32_t mbar) {
    asm volatile("cp.async.bulk.shared::cta.global.mbarrier::complete_tx::bytes [%0], [%1], %2, [%3];"
                 :: "r"(dst), "l"(src), "r"(bytes), "r"(mbar) : "memory");
}

// pack 8 floats -> 16B fp16 hi plane + 16B fp16 lo plane
__device__ __forceinline__ void split8h(const float* v, uint4& hi, uint4& lo) {
    uint32_t h[4], l[4];
#pragma unroll
    for (int i = 0; i < 4; i++) {
        __half a = __float2half_rn(v[2*i]), b = __float2half_rn(v[2*i+1]);
        h[i] = (uint32_t)__half_as_ushort(a) | ((uint32_t)__half_as_ushort(b) << 16);
        l[i] = pack2h(v[2*i] - __half2float(a), v[2*i+1] - __half2float(b));
    }
    hi = make_uint4(h[0], h[1], h[2], h[3]);
    lo = make_uint4(l[0], l[1], l[2], l[3]);
}

// ---------------------------------------------------------------------------
// Kernel 0: zero output + reset counters
// ---------------------------------------------------------------------------
__global__ void zero_kernel(float4* __restrict__ out) {
    int i = blockIdx.x * blockDim.x + threadIdx.x;
    out[i] = make_float4(0.f, 0.f, 0.f, 0.f);
    if (blockIdx.x == 0 && threadIdx.x < EE) g_cnt[threadIdx.x] = 0;
}

// ---------------------------------------------------------------------------
// Kernel 1: router (fp32, validated)
// ---------------------------------------------------------------------------
__global__ __launch_bounds__(256) void router_kernel(const float* __restrict__ x,
                                                     const float* __restrict__ rw) {
    int n = blockIdx.x, tid = threadIdx.x;
    const float* xr = x + (size_t)n * DD;
    float acc[EE];
#pragma unroll
    for (int e = 0; e < EE; e++) acc[e] = 0.f;
    for (int i = tid; i < DD; i += 256) {
        float xv = xr[i];
#pragma unroll
        for (int e = 0; e < EE; e++) acc[e] += xv * rw[e * DD + i];
    }
#pragma unroll
    for (int e = 0; e < EE; e++)
#pragma unroll
        for (int o = 16; o > 0; o >>= 1) acc[e] += __shfl_down_sync(0xffffffffu, acc[e], o);

    __shared__ float sm[8][EE];
    int warp = tid >> 5, lane = tid & 31;
    if (lane == 0)
#pragma unroll
        for (int e = 0; e < EE; e++) sm[warp][e] = acc[e];
    __syncthreads();

    if (tid == 0) {
        float logits[EE];
#pragma unroll
        for (int e = 0; e < EE; e++) {
            float s = 0.f;
#pragma unroll
            for (int w = 0; w < 8; w++) s += sm[w][e];
            logits[e] = s;
        }
        int i0 = 0; float v0 = logits[0];
#pragma unroll
        for (int e = 1; e < EE; e++) if (logits[e] > v0) { v0 = logits[e]; i0 = e; }
        int i1 = 0; float v1 = -3.0e38f;
#pragma unroll
        for (int e = 0; e < EE; e++) if (e != i0 && logits[e] > v1) { v1 = logits[e]; i1 = e; }
        float ex = __expf(v1 - v0);
        float g0 = 1.f / (1.f + ex);
        float g1 = ex * g0;
        int p0 = atomicAdd(&g_cnt[i0], 1);
        g_tok[i0 * NN + p0] = n;  g_gate[i0 * NN + p0] = g0;
        int p1 = atomicAdd(&g_cnt[i1], 1);
        g_tok[i1 * NN + p1] = n;  g_gate[i1 * NN + p1] = g1;
    }
}

// ---------------------------------------------------------------------------
// Kernel 2: gather tokens, split fp16 hi/lo into swizzled tiled A planes
// ---------------------------------------------------------------------------
__global__ __launch_bounds__(128) void gather_kernel(const float* __restrict__ x) {
    int e = blockIdx.y, slot = blockIdx.x;
    int cnt = g_cnt[e];
    int pad = (cnt + 127) & ~127;  if (pad > NN) pad = NN;
    if (slot >= pad) return;
    int mb = slot >> 7, m = slot & 127;
    int t = threadIdx.x;
    int kc = t >> 2, u = t & 3;
    size_t plane = (((size_t)e * 64 + mb) * 32 + kc) * 8192;
    uint32_t off = (uint32_t)m * 64 + (uint32_t)((u ^ ((m >> 1) & 3)) << 4);
    uint8_t* dh = (uint8_t*)g_xg_hi + plane + off;
    uint8_t* dl = (uint8_t*)g_xg_lo + plane + off;
    if (slot < cnt) {
        int tok = g_tok[e * NN + slot];
        const float4* xs = (const float4*)(x + (size_t)tok * DD + t * 8);
        float v[8];
        float4 a = xs[0], b = xs[1];
        v[0]=a.x; v[1]=a.y; v[2]=a.z; v[3]=a.w; v[4]=b.x; v[5]=b.y; v[6]=b.z; v[7]=b.w;
        uint4 hi, lo;
        split8h(v, hi, lo);
        *(uint4*)dh = hi;
        *(uint4*)dl = lo;
    } else {
        uint4 z = make_uint4(0,0,0,0);
        *(uint4*)dh = z;
        *(uint4*)dl = z;
    }
}

// ---------------------------------------------------------------------------
// Kernels 3/4: weights -> transposed, single fp16 swizzled tiled B planes
// w [E][R][C] fp32 -> planes [E][nb=C/128][kc=R/32][8192B]
// grid (R/32, C/256, E), 256 threads
// ---------------------------------------------------------------------------
template<int R, int C, int WHICH>   // WHICH 0 -> g_w1t, 1 -> g_w2t
__global__ __launch_bounds__(256) void wsplit_kernel(const float* __restrict__ w) {
    int kc = blockIdx.x, nb2 = blockIdx.y, e = blockIdx.z;
    const float* src = w + (size_t)e * R * C;
    int t = threadIdx.x;
    int n = nb2 * 256 + t;
    float vals[32];
#pragma unroll
    for (int j = 0; j < 32; j++)
        vals[j] = src[(size_t)(kc * 32 + j) * C + n];
    __half* dst = (WHICH == 0) ? g_w1t : g_w2t;
    int nb = nb2 * 2 + (t >> 7);
    int m  = t & 127;
    size_t plane = (((size_t)e * (C / 128) + nb) * (R / 32) + kc) * 8192;
    int sw = (m >> 1) & 3;
    uint32_t rbase = (uint32_t)m * 64;
#pragma unroll
    for (int u = 0; u < 4; u++) {
        uint4 h4;
        h4.x = pack2h(vals[u*8+0], vals[u*8+1]);
        h4.y = pack2h(vals[u*8+2], vals[u*8+3]);
        h4.z = pack2h(vals[u*8+4], vals[u*8+5]);
        h4.w = pack2h(vals[u*8+6], vals[u*8+7]);
        uint32_t off = rbase + (uint32_t)((u ^ sw) << 4);
        *(uint4*)((uint8_t*)dst + plane + off) = h4;
    }
}

// ---------------------------------------------------------------------------
// fp16 2-pass bulk-fed mma.sync grouped GEMM. occ 2, 4-stage mbarrier pipeline.
// D[128x128] += (Ahi+Alo) * B^T. 256 threads (8 warps, 4Mx2N), warp tile 32x64.
// IS_G1: A = xg planes (K=1024), B = w1t; epilogue relu^2 -> h fp16 hi/lo.
// else:  A = h planes (K=2048, split-K 2), B = w2t; gate*atomicAdd scatter.
// ---------------------------------------------------------------------------
template<int KTOT, int KSLICES, bool IS_G1>
__global__ __launch_bounds__(256, 2) void gemm_mma(float* __restrict__ out) {
    constexpr int KC  = (KTOT / KSLICES) / TK;
    constexpr int NBP = (IS_G1 ? HH : DD) / 128;
    constexpr int KCB = KTOT / 32;
    int zz = blockIdx.z;
    int e = zz & (EE - 1);
    int slice = zz >> 3;
    int kc0 = slice * KC;
    int cnt = g_cnt[e];
    int m0  = blockIdx.y * TM;
    if (m0 >= cnt) return;
    int mb  = blockIdx.y;
    int nb  = blockIdx.x;
    int n0  = nb * TN;

    extern __shared__ char smem[];
    uint32_t sb = smem_u32(smem);
    uint32_t fullb  = sb + NSTAGE * STAGE_BYTES;
    uint32_t emptyb = fullb + 32;

    const uint8_t *pAh, *pAl, *pB;
    {
        size_t ap = (((size_t)e * 64 + mb) * KCB) * 8192;
        size_t bp = (((size_t)e * NBP + nb) * KCB) * 8192;
        if (IS_G1) {
            pAh = (const uint8_t*)g_xg_hi + ap;  pAl = (const uint8_t*)g_xg_lo + ap;
            pB  = (const uint8_t*)g_w1t + bp;
        } else {
            pAh = (const uint8_t*)g_h_hi + ap;   pAl = (const uint8_t*)g_h_lo + ap;
            pB  = (const uint8_t*)g_w2t + bp;
        }
    }

    int tid = threadIdx.x;
    int wid = tid >> 5, lane = tid & 31;

    if (tid == 0) {
#pragma unroll
        for (int s = 0; s < NSTAGE; s++) {
            MBAR_INIT(fullb + s * 8, 1);
            MBAR_INIT(emptyb + s * 8, 8);
        }
    }
    __syncthreads();

    auto issue = [&](int j, int s) {
        uint32_t st = sb + (uint32_t)s * STAGE_BYTES;
        uint32_t mb_s = fullb + s * 8;
        size_t kc = (size_t)(kc0 + j);
        MBAR_EXPECT_TX(mb_s, STAGE_BYTES);
        bulk_g2s(st,         pAh + kc * 8192, 8192, mb_s);
        bulk_g2s(st + A_LO,  pAl + kc * 8192, 8192, mb_s);
        bulk_g2s(st + B_OFF, pB  + kc * 8192, 8192, mb_s);
    };
    if (wid < NSTAGE && lane == 0 && wid < KC) issue(wid, wid);

    // ---- warp / lane geometry: 4 warps M x 2 warps N, warp tile 32x64 ----
    int wm = wid & 3;
    int wn = wid >> 2;
    int li = lane >> 3;
    int lr = lane & 7;
    int kadd = li >> 1;
    int rsel = (li & 1) * 8 + lr;

    uint32_t abase[2]; int asw[2];
#pragma unroll
    for (int mt = 0; mt < 2; mt++) {
        int m = wm * 32 + mt * 16 + rsel;
        abase[mt] = (uint32_t)m * 64;
        asw[mt] = (m >> 1) & 3;
    }
    uint32_t bbase[4]; int bsw[4];
#pragma unroll
    for (int p = 0; p < 4; p++) {
        int n = wn * 64 + p * 16 + rsel;
        bbase[p] = (uint32_t)n * 64;
        bsw[p] = (n >> 1) & 3;
    }

    float acc[2][8][4];
#pragma unroll
    for (int a = 0; a < 2; a++)
#pragma unroll
        for (int b = 0; b < 8; b++)
#pragma unroll
            for (int c = 0; c < 4; c++) acc[a][b][c] = 0.f;

    int s = 0;
    uint32_t ph = 0;
    for (int j = 0; j < KC; j++) {
        MBAR_WAIT(fullb + s * 8, ph);
        uint32_t st = sb + (uint32_t)s * STAGE_BYTES;
#pragma unroll
        for (int kqi = 0; kqi < 2; kqi++) {
            int kq = kqi * 2;
            uint32_t ahi[2][4], alo[2][4];
#pragma unroll
            for (int mt = 0; mt < 2; mt++) {
                uint32_t off = abase[mt] + (uint32_t)((((kq + kadd) ^ asw[mt])) << 4);
                ldsm4(ahi[mt], st + off);
                ldsm4(alo[mt], st + A_LO + off);
            }
#pragma unroll
            for (int p = 0; p < 4; p++) {
                uint32_t bh[4];
                uint32_t off = bbase[p] + (uint32_t)((((kq + kadd) ^ bsw[p])) << 4);
                ldsm4(bh, st + B_OFF + off);
                if (kqi == 1 && p == 3 && lane == 0) MBAR_ARRIVE_REL(emptyb + s * 8);
#pragma unroll
                for (int mt = 0; mt < 2; mt++) {
#pragma unroll
                    for (int sgl = 0; sgl < 2; sgl++) {
                        float* c = acc[mt][p * 2 + sgl];
                        mma_f16(c, ahi[mt], bh[sgl], bh[2 + sgl]);
                        mma_f16(c, alo[mt], bh[sgl], bh[2 + sgl]);
                    }
                }
            }
        }
        if (wid == s && lane == 0 && j + NSTAGE < KC) {
            MBAR_WAIT(emptyb + s * 8, ph);
            issue(j + NSTAGE, s);
        }
        if (++s == NSTAGE) { s = 0; ph ^= 1; }
    }

    // ---- epilogue ----
    int r4 = lane >> 2, cpair = (lane & 3) * 2;
    if (IS_G1) {
        size_t planeH0 = (((size_t)e * 64 + mb) * 64) * 8192;
#pragma unroll
        for (int mt = 0; mt < 2; mt++) {
#pragma unroll
            for (int q = 0; q < 8; q++) {
                int kcH = (n0 >> 5) + wn * 2 + (q >> 2);
                int u = q & 3;
#pragma unroll
                for (int half = 0; half < 2; half++) {
                    int lm = wm * 32 + mt * 16 + r4 + half * 8;
                    float v0 = acc[mt][q][half * 2 + 0];
                    float v1 = acc[mt][q][half * 2 + 1];
                    v0 = fmaxf(v0, 0.f); v0 *= v0;
                    v1 = fmaxf(v1, 0.f); v1 *= v1;
                    __half h0 = __float2half_rn(v0), h1 = __float2half_rn(v1);
                    uint32_t hw = (uint32_t)__half_as_ushort(h0) |
                                  ((uint32_t)__half_as_ushort(h1) << 16);
                    uint32_t lw = pack2h(v0 - __half2float(h0), v1 - __half2float(h1));
                    size_t off = planeH0 + (size_t)kcH * 8192 +
                                 (uint32_t)(lm * 64 + ((u ^ ((lm >> 1) & 3)) << 4) + cpair * 2);
                    *(uint32_t*)((uint8_t*)g_h_hi + off) = hw;
                    *(uint32_t*)((uint8_t*)g_h_lo + off) = lw;
                }
            }
        }
    } else {
#pragma unroll
        for (int mt = 0; mt < 2; mt++) {
            int gm = m0 + wm * 32 + mt * 16;
            int   tokh[2];
            float gth[2];
#pragma unroll
            for (int half = 0; half < 2; half++) {
                int slot = gm + r4 + half * 8;
                bool ok = slot < cnt;
                tokh[half] = ok ? g_tok[e * NN + slot] : -1;
                gth[half]  = ok ? g_gate[e * NN + slot] : 0.f;
            }
#pragma unroll
            for (int q = 0; q < 8; q++) {
                int gn = n0 + wn * 64 + q * 8 + cpair;
#pragma unroll
                for (int half = 0; half < 2; half++) {
                    if (tokh[half] >= 0) {
                        float* orow = out + (size_t)tokh[half] * DD + gn;
                        atomicAdd(orow,     gth[half] * acc[mt][q][half * 2 + 0]);
                        atomicAdd(orow + 1, gth[half] * acc[mt][q][half * 2 + 1]);
                    }
                }
            }
        }
    }
}

// ---------------------------------------------------------------------------
extern "C" void kernel_launch(void* const* d_in, const int* in_sizes, int n_in,
                              void* d_out, int out_size) {
    const float* x  = (const float*)d_in[0];   // (B,T,D)
    const float* rw = (const float*)d_in[1];   // (E,D)
    const float* w1 = (const float*)d_in[2];   // (E,D,H)
    const float* w2 = (const float*)d_in[3];   // (E,H,D)
    float* out = (float*)d_out;                // (B,T,D) fp32

    cudaFuncSetAttribute(gemm_mma<DD, 1, true>,  cudaFuncAttributeMaxDynamicSharedMemorySize, SMEM_BYTES);
    cudaFuncSetAttribute(gemm_mma<HH, 2, false>, cudaFuncAttributeMaxDynamicSharedMemorySize, SMEM_BYTES);

    int zblocks = out_size / (4 * 256);
    zero_kernel<<<zblocks, 256>>>((float4*)out);
    router_kernel<<<NN, 256>>>(x, rw);
    wsplit_kernel<DD, HH, 0><<<dim3(DD / 32, HH / 256, EE), 256>>>(w1);
    wsplit_kernel<HH, DD, 1><<<dim3(HH / 32, DD / 256, EE), 256>>>(w2);
    gather_kernel<<<dim3(NN, EE), 128>>>(x);
    gemm_mma<DD, 1, true><<<dim3(HH / TN, NN / TM, EE), 256, SMEM_BYTES>>>(nullptr);
    gemm_mma<HH, 2, false><<<dim3(DD / TN, NN / TM, EE * 2), 256, SMEM_BYTES>>>(out);
}

// round 14
// speedup vs baseline: 5.0593x; 1.2580x over previous
#include <cuda_runtime.h>
#include <cuda_bf16.h>
#include <cuda_fp16.h>
#include <cstdint>

// ---------------- problem constants ----------------
#define DD   1024
#define EE   8
#define HH   2048
#define NN   8192   // B*T tokens

// GEMM tile config: CTA 128x128, 8 warps (4M x 2N), warp tile 32x64, K-chunk 32
#define TM   128
#define TN   128
#define TK   32
// G1 stage (2-pass A): Ahi8K + Alo8K + B8K = 24KB, 4 stages
// G2 stage (1-pass A): A8K + B8K = 16KB, 6 stages
#define A_LO 8192

// Tiled-plane geometry (all planes 8192B = 128 rows x 64B, swizzled):
//  row byte: m*64 + ((u ^ ((m>>1)&3))<<4) + (k&7)*2,  u = (k>>3)&3

// ---------------- static device scratch ----------------
__device__ int   g_cnt[EE];
__device__ int   g_tok[EE * NN];
__device__ float g_gate[EE * NN];
__device__ __half g_xg_hi[(size_t)EE * NN * DD];   // [e][mb<64][kc<32][8KB] fp16
__device__ __half g_xg_lo[(size_t)EE * NN * DD];
__device__ __half g_h    [(size_t)EE * NN * HH];   // [e][mb<64][kc<64][8KB] fp16 single
__device__ __half g_w1t  [(size_t)EE * DD * HH];   // [e][nb<16][kc<32][8KB] fp16 single
__device__ __half g_w2t  [(size_t)EE * HH * DD];   // [e][nb<8][kc<64][8KB] fp16 single

// ---------------- helpers ----------------
__device__ __forceinline__ uint32_t smem_u32(const void* p) {
    uint32_t a;
    asm("{ .reg .u64 t; cvta.to.shared.u64 t, %1; cvt.u32.u64 %0, t; }" : "=r"(a) : "l"(p));
    return a;
}
__device__ __forceinline__ void ldsm4(uint32_t* r, uint32_t a) {
    asm volatile("ldmatrix.sync.aligned.m8n8.x4.shared.b16 {%0,%1,%2,%3}, [%4];"
                 : "=r"(r[0]), "=r"(r[1]), "=r"(r[2]), "=r"(r[3]) : "r"(a));
}
__device__ __forceinline__ void mma_f16(float* c, const uint32_t* a, uint32_t b0, uint32_t b1) {
    asm volatile("mma.sync.aligned.m16n8k16.row.col.f32.f16.f16.f32 "
                 "{%0,%1,%2,%3}, {%4,%5,%6,%7}, {%8,%9}, {%0,%1,%2,%3};"
                 : "+f"(c[0]), "+f"(c[1]), "+f"(c[2]), "+f"(c[3])
                 : "r"(a[0]), "r"(a[1]), "r"(a[2]), "r"(a[3]), "r"(b0), "r"(b1));
}
__device__ __forceinline__ uint32_t pack2h(float a, float b) {   // fp16 pair
    __half h0 = __float2half_rn(a), h1 = __float2half_rn(b);
    return (uint32_t)__half_as_ushort(h0) | ((uint32_t)__half_as_ushort(h1) << 16);
}
#define MBAR_INIT(a, c) asm volatile("mbarrier.init.shared.b64 [%0], %1;" :: "r"(a), "r"((uint32_t)(c)) : "memory")
#define MBAR_EXPECT_TX(a, tx) asm volatile("mbarrier.arrive.expect_tx.shared.b64 _, [%0], %1;" :: "r"(a), "r"((uint32_t)(tx)) : "memory")
#define MBAR_ARRIVE_REL(a) asm volatile("mbarrier.arrive.release.cta.shared::cta.b64 _, [%0];" :: "r"(a) : "memory")
#define MBAR_WAIT(a, ph) do { \
    uint32_t _m = (a); uint32_t _p = (uint32_t)(ph); uint32_t _d; \
    asm volatile("{\n\t.reg .pred p;\n\tmbarrier.try_wait.parity.acquire.cta.shared::cta.b64 p, [%1], %2;\n\tselp.b32 %0,1,0,p;\n\t}" \
        : "=r"(_d) : "r"(_m), "r"(_p) : "memory"); \
    if (!_d) { \
        asm volatile("{\n\t.reg .pred P1;\n\tWL_%=:\n\tmbarrier.try_wait.parity.acquire.cta.shared::cta.b64 P1, [%0], %1, 0x989680;\n\t@P1 bra.uni WD_%=;\n\tbra.uni WL_%=;\n\tWD_%=:\n\t}" \
            :: "r"(_m), "r"(_p) : "memory"); \
    } } while (0)
__device__ __forceinline__ void bulk_g2s(uint32_t dst, const void* src, uint32_t bytes, uint32_t mbar) {
    asm volatile("cp.async.bulk.shared::cta.global.mbarrier::complete_tx::bytes [%0], [%1], %2, [%3];"
                 :: "r"(dst), "l"(src), "r"(bytes), "r"(mbar) : "memory");
}

// pack 8 floats -> 16B fp16 hi plane + 16B fp16 lo plane
__device__ __forceinline__ void split8h(const float* v, uint4& hi, uint4& lo) {
    uint32_t h[4], l[4];
#pragma unroll
    for (int i = 0; i < 4; i++) {
        __half a = __float2half_rn(v[2*i]), b = __float2half_rn(v[2*i+1]);
        h[i] = (uint32_t)__half_as_ushort(a) | ((uint32_t)__half_as_ushort(b) << 16);
        l[i] = pack2h(v[2*i] - __half2float(a), v[2*i+1] - __half2float(b));
    }
    hi = make_uint4(h[0], h[1], h[2], h[3]);
    lo = make_uint4(l[0], l[1], l[2], l[3]);
}

// ---------------------------------------------------------------------------
// Kernel 0: zero output + reset counters
// ---------------------------------------------------------------------------
__global__ void zero_kernel(float4* __restrict__ out) {
    int i = blockIdx.x * blockDim.x + threadIdx.x;
    out[i] = make_float4(0.f, 0.f, 0.f, 0.f);
    if (blockIdx.x == 0 && threadIdx.x < EE) g_cnt[threadIdx.x] = 0;
}

// ---------------------------------------------------------------------------
// Kernel 1: router (fp32, validated)
// ---------------------------------------------------------------------------
__global__ __launch_bounds__(256) void router_kernel(const float* __restrict__ x,
                                                     const float* __restrict__ rw) {
    int n = blockIdx.x, tid = threadIdx.x;
    const float* xr = x + (size_t)n * DD;
    float acc[EE];
#pragma unroll
    for (int e = 0; e < EE; e++) acc[e] = 0.f;
    for (int i = tid; i < DD; i += 256) {
        float xv = xr[i];
#pragma unroll
        for (int e = 0; e < EE; e++) acc[e] += xv * rw[e * DD + i];
    }
#pragma unroll
    for (int e = 0; e < EE; e++)
#pragma unroll
        for (int o = 16; o > 0; o >>= 1) acc[e] += __shfl_down_sync(0xffffffffu, acc[e], o);

    __shared__ float sm[8][EE];
    int warp = tid >> 5, lane = tid & 31;
    if (lane == 0)
#pragma unroll
        for (int e = 0; e < EE; e++) sm[warp][e] = acc[e];
    __syncthreads();

    if (tid == 0) {
        float logits[EE];
#pragma unroll
        for (int e = 0; e < EE; e++) {
            float s = 0.f;
#pragma unroll
            for (int w = 0; w < 8; w++) s += sm[w][e];
            logits[e] = s;
        }
        int i0 = 0; float v0 = logits[0];
#pragma unroll
        for (int e = 1; e < EE; e++) if (logits[e] > v0) { v0 = logits[e]; i0 = e; }
        int i1 = 0; float v1 = -3.0e38f;
#pragma unroll
        for (int e = 0; e < EE; e++) if (e != i0 && logits[e] > v1) { v1 = logits[e]; i1 = e; }
        float ex = __expf(v1 - v0);
        float g0 = 1.f / (1.f + ex);
        float g1 = ex * g0;
        int p0 = atomicAdd(&g_cnt[i0], 1);
        g_tok[i0 * NN + p0] = n;  g_gate[i0 * NN + p0] = g0;
        int p1 = atomicAdd(&g_cnt[i1], 1);
        g_tok[i1 * NN + p1] = n;  g_gate[i1 * NN + p1] = g1;
    }
}

// ---------------------------------------------------------------------------
// Kernel 2: gather tokens, split fp16 hi/lo into swizzled tiled A planes
// ---------------------------------------------------------------------------
__global__ __launch_bounds__(128) void gather_kernel(const float* __restrict__ x) {
    int e = blockIdx.y, slot = blockIdx.x;
    int cnt = g_cnt[e];
    int pad = (cnt + 127) & ~127;  if (pad > NN) pad = NN;
    if (slot >= pad) return;
    int mb = slot >> 7, m = slot & 127;
    int t = threadIdx.x;
    int kc = t >> 2, u = t & 3;
    size_t plane = (((size_t)e * 64 + mb) * 32 + kc) * 8192;
    uint32_t off = (uint32_t)m * 64 + (uint32_t)((u ^ ((m >> 1) & 3)) << 4);
    uint8_t* dh = (uint8_t*)g_xg_hi + plane + off;
    uint8_t* dl = (uint8_t*)g_xg_lo + plane + off;
    if (slot < cnt) {
        int tok = g_tok[e * NN + slot];
        const float4* xs = (const float4*)(x + (size_t)tok * DD + t * 8);
        float v[8];
        float4 a = xs[0], b = xs[1];
        v[0]=a.x; v[1]=a.y; v[2]=a.z; v[3]=a.w; v[4]=b.x; v[5]=b.y; v[6]=b.z; v[7]=b.w;
        uint4 hi, lo;
        split8h(v, hi, lo);
        *(uint4*)dh = hi;
        *(uint4*)dl = lo;
    } else {
        uint4 z = make_uint4(0,0,0,0);
        *(uint4*)dh = z;
        *(uint4*)dl = z;
    }
}

// ---------------------------------------------------------------------------
// Kernels 3/4: weights -> transposed, single fp16 swizzled tiled B planes
// ---------------------------------------------------------------------------
template<int R, int C, int WHICH>   // WHICH 0 -> g_w1t, 1 -> g_w2t
__global__ __launch_bounds__(256) void wsplit_kernel(const float* __restrict__ w) {
    int kc = blockIdx.x, nb2 = blockIdx.y, e = blockIdx.z;
    const float* src = w + (size_t)e * R * C;
    int t = threadIdx.x;
    int n = nb2 * 256 + t;
    float vals[32];
#pragma unroll
    for (int j = 0; j < 32; j++)
        vals[j] = src[(size_t)(kc * 32 + j) * C + n];
    __half* dst = (WHICH == 0) ? g_w1t : g_w2t;
    int nb = nb2 * 2 + (t >> 7);
    int m  = t & 127;
    size_t plane = (((size_t)e * (C / 128) + nb) * (R / 32) + kc) * 8192;
    int sw = (m >> 1) & 3;
    uint32_t rbase = (uint32_t)m * 64;
#pragma unroll
    for (int u = 0; u < 4; u++) {
        uint4 h4;
        h4.x = pack2h(vals[u*8+0], vals[u*8+1]);
        h4.y = pack2h(vals[u*8+2], vals[u*8+3]);
        h4.z = pack2h(vals[u*8+4], vals[u*8+5]);
        h4.w = pack2h(vals[u*8+6], vals[u*8+7]);
        uint32_t off = rbase + (uint32_t)((u ^ sw) << 4);
        *(uint4*)((uint8_t*)dst + plane + off) = h4;
    }
}

// ---------------------------------------------------------------------------
// bulk-fed mma.sync grouped GEMM. occ 2, mbarrier pipeline, 8 warps (4Mx2N).
// IS_G1: A = xg hi/lo (2-pass, K=1024), 24KB stage x4; relu^2 -> g_h fp16.
// else:  A = g_h single (1-pass, K=2048, split-K 2), 16KB stage x6; scatter.
// ---------------------------------------------------------------------------
template<int KTOT, int KSLICES, bool IS_G1>
__global__ __launch_bounds__(256, 2) void gemm_mma(float* __restrict__ out) {
    constexpr int KC    = (KTOT / KSLICES) / TK;
    constexpr int NBP   = (IS_G1 ? HH : DD) / 128;
    constexpr int KCB   = KTOT / 32;
    constexpr int NST   = IS_G1 ? 4 : 6;
    constexpr int STAGE = IS_G1 ? 24576 : 16384;
    constexpr int B_OFF = IS_G1 ? 16384 : 8192;
    int zz = blockIdx.z;
    int e = zz & (EE - 1);
    int slice = zz >> 3;
    int kc0 = slice * KC;
    int cnt = g_cnt[e];
    int m0  = blockIdx.y * TM;
    if (m0 >= cnt) return;
    int mb  = blockIdx.y;
    int nb  = blockIdx.x;
    int n0  = nb * TN;

    extern __shared__ char smem[];
    uint32_t sb = smem_u32(smem);
    uint32_t fullb  = sb + NST * STAGE;
    uint32_t emptyb = fullb + 48;

    const uint8_t *pAh, *pAl, *pB;
    {
        size_t ap = (((size_t)e * 64 + mb) * KCB) * 8192;
        size_t bp = (((size_t)e * NBP + nb) * KCB) * 8192;
        if (IS_G1) {
            pAh = (const uint8_t*)g_xg_hi + ap;
            pAl = (const uint8_t*)g_xg_lo + ap;
            pB  = (const uint8_t*)g_w1t + bp;
        } else {
            pAh = (const uint8_t*)g_h + ap;
            pAl = nullptr;
            pB  = (const uint8_t*)g_w2t + bp;
        }
    }

    int tid = threadIdx.x;
    int wid = tid >> 5, lane = tid & 31;

    if (tid == 0) {
#pragma unroll
        for (int s = 0; s < NST; s++) {
            MBAR_INIT(fullb + s * 8, 1);
            MBAR_INIT(emptyb + s * 8, 8);
        }
    }
    __syncthreads();

    auto issue = [&](int j, int s) {
        uint32_t st = sb + (uint32_t)s * STAGE;
        uint32_t mb_s = fullb + s * 8;
        size_t kc = (size_t)(kc0 + j);
        MBAR_EXPECT_TX(mb_s, STAGE);
        bulk_g2s(st, pAh + kc * 8192, 8192, mb_s);
        if (IS_G1) bulk_g2s(st + A_LO, pAl + kc * 8192, 8192, mb_s);
        bulk_g2s(st + B_OFF, pB + kc * 8192, 8192, mb_s);
    };
    if (wid < NST && lane == 0 && wid < KC) issue(wid, wid);

    // ---- warp / lane geometry: 4 warps M x 2 warps N, warp tile 32x64 ----
    int wm = wid & 3;
    int wn = wid >> 2;
    int li = lane >> 3;
    int lr = lane & 7;
    int kadd = li >> 1;
    int rsel = (li & 1) * 8 + lr;

    uint32_t abase[2]; int asw[2];
#pragma unroll
    for (int mt = 0; mt < 2; mt++) {
        int m = wm * 32 + mt * 16 + rsel;
        abase[mt] = (uint32_t)m * 64;
        asw[mt] = (m >> 1) & 3;
    }
    uint32_t bbase[4]; int bsw[4];
#pragma unroll
    for (int p = 0; p < 4; p++) {
        int n = wn * 64 + p * 16 + rsel;
        bbase[p] = (uint32_t)n * 64;
        bsw[p] = (n >> 1) & 3;
    }

    float acc[2][8][4];
#pragma unroll
    for (int a = 0; a < 2; a++)
#pragma unroll
        for (int b = 0; b < 8; b++)
#pragma unroll
            for (int c = 0; c < 4; c++) acc[a][b][c] = 0.f;

    int s = 0;
    uint32_t ph = 0;
    for (int j = 0; j < KC; j++) {
        MBAR_WAIT(fullb + s * 8, ph);
        uint32_t st = sb + (uint32_t)s * STAGE;
#pragma unroll
        for (int kqi = 0; kqi < 2; kqi++) {
            int kq = kqi * 2;
            uint32_t ahi[2][4], alo[2][4];
#pragma unroll
            for (int mt = 0; mt < 2; mt++) {
                uint32_t off = abase[mt] + (uint32_t)((((kq + kadd) ^ asw[mt])) << 4);
                ldsm4(ahi[mt], st + off);
                if (IS_G1) ldsm4(alo[mt], st + A_LO + off);
            }
#pragma unroll
            for (int p = 0; p < 4; p++) {
                uint32_t bh[4];
                uint32_t off = bbase[p] + (uint32_t)((((kq + kadd) ^ bsw[p])) << 4);
                ldsm4(bh, st + B_OFF + off);
                if (kqi == 1 && p == 3 && lane == 0) MBAR_ARRIVE_REL(emptyb + s * 8);
#pragma unroll
                for (int mt = 0; mt < 2; mt++) {
#pragma unroll
                    for (int sgl = 0; sgl < 2; sgl++) {
                        float* c = acc[mt][p * 2 + sgl];
                        mma_f16(c, ahi[mt], bh[sgl], bh[2 + sgl]);
                        if (IS_G1) mma_f16(c, alo[mt], bh[sgl], bh[2 + sgl]);
                    }
                }
            }
        }
        if (wid == s && lane == 0 && j + NST < KC) {
            MBAR_WAIT(emptyb + s * 8, ph);
            issue(j + NST, s);
        }
        if (++s == NST) { s = 0; ph ^= 1; }
    }

    // ---- epilogue ----
    int r4 = lane >> 2, cpair = (lane & 3) * 2;
    if (IS_G1) {
        size_t planeH0 = (((size_t)e * 64 + mb) * 64) * 8192;
#pragma unroll
        for (int mt = 0; mt < 2; mt++) {
#pragma unroll
            for (int q = 0; q < 8; q++) {
                int kcH = (n0 >> 5) + wn * 2 + (q >> 2);
                int u = q & 3;
#pragma unroll
                for (int half = 0; half < 2; half++) {
                    int lm = wm * 32 + mt * 16 + r4 + half * 8;
                    float v0 = acc[mt][q][half * 2 + 0];
                    float v1 = acc[mt][q][half * 2 + 1];
                    v0 = fmaxf(v0, 0.f); v0 *= v0;
                    v1 = fmaxf(v1, 0.f); v1 *= v1;
                    uint32_t hw = pack2h(v0, v1);
                    size_t off = planeH0 + (size_t)kcH * 8192 +
                                 (uint32_t)(lm * 64 + ((u ^ ((lm >> 1) & 3)) << 4) + cpair * 2);
                    *(uint32_t*)((uint8_t*)g_h + off) = hw;
                }
            }
        }
    } else {
#pragma unroll
        for (int mt = 0; mt < 2; mt++) {
            int gm = m0 + wm * 32 + mt * 16;
            int   tokh[2];
            float gth[2];
#pragma unroll
            for (int half = 0; half < 2; half++) {
                int slot = gm + r4 + half * 8;
                bool ok = slot < cnt;
                tokh[half] = ok ? g_tok[e * NN + slot] : -1;
                gth[half]  = ok ? g_gate[e * NN + slot] : 0.f;
            }
#pragma unroll
            for (int q = 0; q < 8; q++) {
                int gn = n0 + wn * 64 + q * 8 + cpair;
#pragma unroll
                for (int half = 0; half < 2; half++) {
                    if (tokh[half] >= 0) {
                        float* orow = out + (size_t)tokh[half] * DD + gn;
                        atomicAdd(orow,     gth[half] * acc[mt][q][half * 2 + 0]);
                        atomicAdd(orow + 1, gth[half] * acc[mt][q][half * 2 + 1]);
                    }
                }
            }
        }
    }
}

// ---------------------------------------------------------------------------
extern "C" void kernel_launch(void* const* d_in, const int* in_sizes, int n_in,
                              void* d_out, int out_size) {
    const float* x  = (const float*)d_in[0];   // (B,T,D)
    const float* rw = (const float*)d_in[1];   // (E,D)
    const float* w1 = (const float*)d_in[2];   // (E,D,H)
    const float* w2 = (const float*)d_in[3];   // (E,H,D)
    float* out = (float*)d_out;                // (B,T,D) fp32

    constexpr int SMEM_G1 = 4 * 24576 + 96;
    constexpr int SMEM_G2 = 6 * 16384 + 96;
    cudaFuncSetAttribute(gemm_mma<DD, 1, true>,  cudaFuncAttributeMaxDynamicSharedMemorySize, SMEM_G1);
    cudaFuncSetAttribute(gemm_mma<HH, 2, false>, cudaFuncAttributeMaxDynamicSharedMemorySize, SMEM_G2);

    int zblocks = out_size / (4 * 256);
    zero_kernel<<<zblocks, 256>>>((float4*)out);
    router_kernel<<<NN, 256>>>(x, rw);
    wsplit_kernel<DD, HH, 0><<<dim3(DD / 32, HH / 256, EE), 256>>>(w1);
    wsplit_kernel<HH, DD, 1><<<dim3(HH / 32, DD / 256, EE), 256>>>(w2);
    gather_kernel<<<dim3(NN, EE), 128>>>(x);
    gemm_mma<DD, 1, true><<<dim3(HH / TN, NN / TM, EE), 256, SMEM_G1>>>(nullptr);
    gemm_mma<HH, 2, false><<<dim3(DD / TN, NN / TM, EE * 2), 256, SMEM_G2>>>(out);
}

// round 15
// speedup vs baseline: 6.5236x; 1.2894x over previous
#include <cuda_runtime.h>
#include <cuda_bf16.h>
#include <cuda_fp16.h>
#include <cstdint>

// ---------------- problem constants ----------------
#define DD   1024
#define EE   8
#define HH   2048
#define NN   8192   // B*T tokens

// GEMM tile config: CTA 128x128, 8 warps (4M x 2N), warp tile 32x64, K-chunk 32
#define TM   128
#define TN   128
#define TK   32
// 1-pass stage: A8K + B8K = 16KB, 6 stages
#define B_OFF 8192
#define STAGE 16384
#define NST   6
#define SMEM_GEMM (NST*STAGE + 96)

// Tiled-plane geometry (all planes 8192B = 128 rows x 64B, swizzled):
//  row byte: m*64 + ((u ^ ((m>>1)&3))<<4) + (k&7)*2,  u = (k>>3)&3

// ---------------- static device scratch ----------------
__device__ int   g_cnt[EE];
__device__ int   g_tok[EE * NN];
__device__ float g_gate[EE * NN];
__device__ __half g_xg  [(size_t)EE * NN * DD];   // [e][mb<64][kc<32][8KB] fp16 single
__device__ __half g_h   [(size_t)EE * NN * HH];   // [e][mb<64][kc<64][8KB] fp16 single
__device__ __half g_w1t [(size_t)EE * DD * HH];   // [e][nb<16][kc<32][8KB] fp16 single
__device__ __half g_w2t [(size_t)EE * HH * DD];   // [e][nb<8][kc<64][8KB] fp16 single

// ---------------- helpers ----------------
__device__ __forceinline__ uint32_t smem_u32(const void* p) {
    uint32_t a;
    asm("{ .reg .u64 t; cvta.to.shared.u64 t, %1; cvt.u32.u64 %0, t; }" : "=r"(a) : "l"(p));
    return a;
}
__device__ __forceinline__ void ldsm4(uint32_t* r, uint32_t a) {
    asm volatile("ldmatrix.sync.aligned.m8n8.x4.shared.b16 {%0,%1,%2,%3}, [%4];"
                 : "=r"(r[0]), "=r"(r[1]), "=r"(r[2]), "=r"(r[3]) : "r"(a));
}
__device__ __forceinline__ void mma_f16(float* c, const uint32_t* a, uint32_t b0, uint32_t b1) {
    asm volatile("mma.sync.aligned.m16n8k16.row.col.f32.f16.f16.f32 "
                 "{%0,%1,%2,%3}, {%4,%5,%6,%7}, {%8,%9}, {%0,%1,%2,%3};"
                 : "+f"(c[0]), "+f"(c[1]), "+f"(c[2]), "+f"(c[3])
                 : "r"(a[0]), "r"(a[1]), "r"(a[2]), "r"(a[3]), "r"(b0), "r"(b1));
}
__device__ __forceinline__ uint32_t pack2h(float a, float b) {   // fp16 pair
    __half h0 = __float2half_rn(a), h1 = __float2half_rn(b);
    return (uint32_t)__half_as_ushort(h0) | ((uint32_t)__half_as_ushort(h1) << 16);
}
#define MBAR_INIT(a, c) asm volatile("mbarrier.init.shared.b64 [%0], %1;" :: "r"(a), "r"((uint32_t)(c)) : "memory")
#define MBAR_EXPECT_TX(a, tx) asm volatile("mbarrier.arrive.expect_tx.shared.b64 _, [%0], %1;" :: "r"(a), "r"((uint32_t)(tx)) : "memory")
#define MBAR_ARRIVE_REL(a) asm volatile("mbarrier.arrive.release.cta.shared::cta.b64 _, [%0];" :: "r"(a) : "memory")
#define MBAR_WAIT(a, ph) do { \
    uint32_t _m = (a); uint32_t _p = (uint32_t)(ph); uint32_t _d; \
    asm volatile("{\n\t.reg .pred p;\n\tmbarrier.try_wait.parity.acquire.cta.shared::cta.b64 p, [%1], %2;\n\tselp.b32 %0,1,0,p;\n\t}" \
        : "=r"(_d) : "r"(_m), "r"(_p) : "memory"); \
    if (!_d) { \
        asm volatile("{\n\t.reg .pred P1;\n\tWL_%=:\n\tmbarrier.try_wait.parity.acquire.cta.shared::cta.b64 P1, [%0], %1, 0x989680;\n\t@P1 bra.uni WD_%=;\n\tbra.uni WL_%=;\n\tWD_%=:\n\t}" \
            :: "r"(_m), "r"(_p) : "memory"); \
    } } while (0)
__device__ __forceinline__ void bulk_g2s(uint32_t dst, const void* src, uint32_t bytes, uint32_t mbar) {
    asm volatile("cp.async.bulk.shared::cta.global.mbarrier::complete_tx::bytes [%0], [%1], %2, [%3];"
                 :: "r"(dst), "l"(src), "r"(bytes), "r"(mbar) : "memory");
}

// ---------------------------------------------------------------------------
// Kernel 0: zero output + reset counters
// ---------------------------------------------------------------------------
__global__ void zero_kernel(float4* __restrict__ out) {
    int i = blockIdx.x * blockDim.x + threadIdx.x;
    out[i] = make_float4(0.f, 0.f, 0.f, 0.f);
    if (blockIdx.x == 0 && threadIdx.x < EE) g_cnt[threadIdx.x] = 0;
}

// ---------------------------------------------------------------------------
// Kernel 1: router (fp32, validated)
// ---------------------------------------------------------------------------
__global__ __launch_bounds__(256) void router_kernel(const float* __restrict__ x,
                                                     const float* __restrict__ rw) {
    int n = blockIdx.x, tid = threadIdx.x;
    const float* xr = x + (size_t)n * DD;
    float acc[EE];
#pragma unroll
    for (int e = 0; e < EE; e++) acc[e] = 0.f;
    for (int i = tid; i < DD; i += 256) {
        float xv = xr[i];
#pragma unroll
        for (int e = 0; e < EE; e++) acc[e] += xv * rw[e * DD + i];
    }
#pragma unroll
    for (int e = 0; e < EE; e++)
#pragma unroll
        for (int o = 16; o > 0; o >>= 1) acc[e] += __shfl_down_sync(0xffffffffu, acc[e], o);

    __shared__ float sm[8][EE];
    int warp = tid >> 5, lane = tid & 31;
    if (lane == 0)
#pragma unroll
        for (int e = 0; e < EE; e++) sm[warp][e] = acc[e];
    __syncthreads();

    if (tid == 0) {
        float logits[EE];
#pragma unroll
        for (int e = 0; e < EE; e++) {
            float s = 0.f;
#pragma unroll
            for (int w = 0; w < 8; w++) s += sm[w][e];
            logits[e] = s;
        }
        int i0 = 0; float v0 = logits[0];
#pragma unroll
        for (int e = 1; e < EE; e++) if (logits[e] > v0) { v0 = logits[e]; i0 = e; }
        int i1 = 0; float v1 = -3.0e38f;
#pragma unroll
        for (int e = 0; e < EE; e++) if (e != i0 && logits[e] > v1) { v1 = logits[e]; i1 = e; }
        float ex = __expf(v1 - v0);
        float g0 = 1.f / (1.f + ex);
        float g1 = ex * g0;
        int p0 = atomicAdd(&g_cnt[i0], 1);
        g_tok[i0 * NN + p0] = n;  g_gate[i0 * NN + p0] = g0;
        int p1 = atomicAdd(&g_cnt[i1], 1);
        g_tok[i1 * NN + p1] = n;  g_gate[i1 * NN + p1] = g1;
    }
}

// ---------------------------------------------------------------------------
// Kernel 2: gather tokens, fp16 quantize into swizzled tiled A planes (single)
// grid (NN, EE), 128 threads: thread t -> kc = t>>2, u = t&3 (16B)
// ---------------------------------------------------------------------------
__global__ __launch_bounds__(128) void gather_kernel(const float* __restrict__ x) {
    int e = blockIdx.y, slot = blockIdx.x;
    int cnt = g_cnt[e];
    int pad = (cnt + 127) & ~127;  if (pad > NN) pad = NN;
    if (slot >= pad) return;
    int mb = slot >> 7, m = slot & 127;
    int t = threadIdx.x;
    int kc = t >> 2, u = t & 3;
    size_t plane = (((size_t)e * 64 + mb) * 32 + kc) * 8192;
    uint32_t off = (uint32_t)m * 64 + (uint32_t)((u ^ ((m >> 1) & 3)) << 4);
    uint8_t* dh = (uint8_t*)g_xg + plane + off;
    if (slot < cnt) {
        int tok = g_tok[e * NN + slot];
        const float4* xs = (const float4*)(x + (size_t)tok * DD + t * 8);
        float4 a = xs[0], b = xs[1];
        uint4 hi;
        hi.x = pack2h(a.x, a.y);
        hi.y = pack2h(a.z, a.w);
        hi.z = pack2h(b.x, b.y);
        hi.w = pack2h(b.z, b.w);
        *(uint4*)dh = hi;
    } else {
        *(uint4*)dh = make_uint4(0, 0, 0, 0);
    }
}

// ---------------------------------------------------------------------------
// Kernels 3/4: weights -> transposed, single fp16 swizzled tiled B planes
// w [E][R][C] fp32 -> planes [E][nb=C/128][kc=R/32][8192B]
// grid (R/32, C/256, E), 256 threads
// ---------------------------------------------------------------------------
template<int R, int C, int WHICH>   // WHICH 0 -> g_w1t, 1 -> g_w2t
__global__ __launch_bounds__(256) void wsplit_kernel(const float* __restrict__ w) {
    int kc = blockIdx.x, nb2 = blockIdx.y, e = blockIdx.z;
    const float* src = w + (size_t)e * R * C;
    int t = threadIdx.x;
    int n = nb2 * 256 + t;
    float vals[32];
#pragma unroll
    for (int j = 0; j < 32; j++)
        vals[j] = src[(size_t)(kc * 32 + j) * C + n];
    __half* dst = (WHICH == 0) ? g_w1t : g_w2t;
    int nb = nb2 * 2 + (t >> 7);
    int m  = t & 127;
    size_t plane = (((size_t)e * (C / 128) + nb) * (R / 32) + kc) * 8192;
    int sw = (m >> 1) & 3;
    uint32_t rbase = (uint32_t)m * 64;
#pragma unroll
    for (int u = 0; u < 4; u++) {
        uint4 h4;
        h4.x = pack2h(vals[u*8+0], vals[u*8+1]);
        h4.y = pack2h(vals[u*8+2], vals[u*8+3]);
        h4.z = pack2h(vals[u*8+4], vals[u*8+5]);
        h4.w = pack2h(vals[u*8+6], vals[u*8+7]);
        uint32_t off = rbase + (uint32_t)((u ^ sw) << 4);
        *(uint4*)((uint8_t*)dst + plane + off) = h4;
    }
}

// ---------------------------------------------------------------------------
// 1-pass fp16 bulk-fed mma.sync grouped GEMM. occ 2, 6-stage mbarrier pipeline.
// D[128x128] += A * B^T. 256 threads (8 warps, 4Mx2N), warp tile 32x64.
// IS_G1: A = xg (K=1024), B = w1t; epilogue relu^2 -> g_h fp16.
// else:  A = g_h (K=2048, split-K 2), B = w2t; gate*atomicAdd scatter.
// ---------------------------------------------------------------------------
template<int KTOT, int KSLICES, bool IS_G1>
__global__ __launch_bounds__(256, 2) void gemm_mma(float* __restrict__ out) {
    constexpr int KC  = (KTOT / KSLICES) / TK;
    constexpr int NBP = (IS_G1 ? HH : DD) / 128;
    constexpr int KCB = KTOT / 32;
    int zz = blockIdx.z;
    int e = zz & (EE - 1);
    int slice = zz >> 3;
    int kc0 = slice * KC;
    int cnt = g_cnt[e];
    int m0  = blockIdx.y * TM;
    if (m0 >= cnt) return;
    int mb  = blockIdx.y;
    int nb  = blockIdx.x;
    int n0  = nb * TN;

    extern __shared__ char smem[];
    uint32_t sb = smem_u32(smem);
    uint32_t fullb  = sb + NST * STAGE;
    uint32_t emptyb = fullb + 48;

    const uint8_t *pA, *pB;
    {
        size_t ap = (((size_t)e * 64 + mb) * KCB) * 8192;
        size_t bp = (((size_t)e * NBP + nb) * KCB) * 8192;
        if (IS_G1) {
            pA = (const uint8_t*)g_xg + ap;
            pB = (const uint8_t*)g_w1t + bp;
        } else {
            pA = (const uint8_t*)g_h + ap;
            pB = (const uint8_t*)g_w2t + bp;
        }
    }

    int tid = threadIdx.x;
    int wid = tid >> 5, lane = tid & 31;

    if (tid == 0) {
#pragma unroll
        for (int s = 0; s < NST; s++) {
            MBAR_INIT(fullb + s * 8, 1);
            MBAR_INIT(emptyb + s * 8, 8);
        }
    }
    __syncthreads();

    auto issue = [&](int j, int s) {
        uint32_t st = sb + (uint32_t)s * STAGE;
        uint32_t mb_s = fullb + s * 8;
        size_t kc = (size_t)(kc0 + j);
        MBAR_EXPECT_TX(mb_s, STAGE);
        bulk_g2s(st,         pA + kc * 8192, 8192, mb_s);
        bulk_g2s(st + B_OFF, pB + kc * 8192, 8192, mb_s);
    };
    if (wid < NST && lane == 0 && wid < KC) issue(wid, wid);

    // ---- warp / lane geometry: 4 warps M x 2 warps N, warp tile 32x64 ----
    int wm = wid & 3;
    int wn = wid >> 2;
    int li = lane >> 3;
    int lr = lane & 7;
    int kadd = li >> 1;
    int rsel = (li & 1) * 8 + lr;

    uint32_t abase[2]; int asw[2];
#pragma unroll
    for (int mt = 0; mt < 2; mt++) {
        int m = wm * 32 + mt * 16 + rsel;
        abase[mt] = (uint32_t)m * 64;
        asw[mt] = (m >> 1) & 3;
    }
    uint32_t bbase[4]; int bsw[4];
#pragma unroll
    for (int p = 0; p < 4; p++) {
        int n = wn * 64 + p * 16 + rsel;
        bbase[p] = (uint32_t)n * 64;
        bsw[p] = (n >> 1) & 3;
    }

    float acc[2][8][4];
#pragma unroll
    for (int a = 0; a < 2; a++)
#pragma unroll
        for (int b = 0; b < 8; b++)
#pragma unroll
            for (int c = 0; c < 4; c++) acc[a][b][c] = 0.f;

    int s = 0;
    uint32_t ph = 0;
    for (int j = 0; j < KC; j++) {
        MBAR_WAIT(fullb + s * 8, ph);
        uint32_t st = sb + (uint32_t)s * STAGE;
#pragma unroll
        for (int kqi = 0; kqi < 2; kqi++) {
            int kq = kqi * 2;
            uint32_t ar[2][4];
#pragma unroll
            for (int mt = 0; mt < 2; mt++) {
                uint32_t off = abase[mt] + (uint32_t)((((kq + kadd) ^ asw[mt])) << 4);
                ldsm4(ar[mt], st + off);
            }
#pragma unroll
            for (int p = 0; p < 4; p++) {
                uint32_t bh[4];
                uint32_t off = bbase[p] + (uint32_t)((((kq + kadd) ^ bsw[p])) << 4);
                ldsm4(bh, st + B_OFF + off);
                if (kqi == 1 && p == 3 && lane == 0) MBAR_ARRIVE_REL(emptyb + s * 8);
#pragma unroll
                for (int mt = 0; mt < 2; mt++) {
#pragma unroll
                    for (int sgl = 0; sgl < 2; sgl++) {
                        float* c = acc[mt][p * 2 + sgl];
                        mma_f16(c, ar[mt], bh[sgl], bh[2 + sgl]);
                    }
                }
            }
        }
        if (wid == s && lane == 0 && j + NST < KC) {
            MBAR_WAIT(emptyb + s * 8, ph);
            issue(j + NST, s);
        }
        if (++s == NST) { s = 0; ph ^= 1; }
    }

    // ---- epilogue ----
    int r4 = lane >> 2, cpair = (lane & 3) * 2;
    if (IS_G1) {
        size_t planeH0 = (((size_t)e * 64 + mb) * 64) * 8192;
#pragma unroll
        for (int mt = 0; mt < 2; mt++) {
#pragma unroll
            for (int q = 0; q < 8; q++) {
                int kcH = (n0 >> 5) + wn * 2 + (q >> 2);
                int u = q & 3;
#pragma unroll
                for (int half = 0; half < 2; half++) {
                    int lm = wm * 32 + mt * 16 + r4 + half * 8;
                    float v0 = acc[mt][q][half * 2 + 0];
                    float v1 = acc[mt][q][half * 2 + 1];
                    v0 = fmaxf(v0, 0.f); v0 *= v0;
                    v1 = fmaxf(v1, 0.f); v1 *= v1;
                    uint32_t hw = pack2h(v0, v1);
                    size_t off = planeH0 + (size_t)kcH * 8192 +
                                 (uint32_t)(lm * 64 + ((u ^ ((lm >> 1) & 3)) << 4) + cpair * 2);
                    *(uint32_t*)((uint8_t*)g_h + off) = hw;
                }
            }
        }
    } else {
#pragma unroll
        for (int mt = 0; mt < 2; mt++) {
            int gm = m0 + wm * 32 + mt * 16;
            int   tokh[2];
            float gth[2];
#pragma unroll
            for (int half = 0; half < 2; half++) {
                int slot = gm + r4 + half * 8;
                bool ok = slot < cnt;
                tokh[half] = ok ? g_tok[e * NN + slot] : -1;
                gth[half]  = ok ? g_gate[e * NN + slot] : 0.f;
            }
#pragma unroll
            for (int q = 0; q < 8; q++) {
                int gn = n0 + wn * 64 + q * 8 + cpair;
#pragma unroll
                for (int half = 0; half < 2; half++) {
                    if (tokh[half] >= 0) {
                        float* orow = out + (size_t)tokh[half] * DD + gn;
                        atomicAdd(orow,     gth[half] * acc[mt][q][half * 2 + 0]);
                        atomicAdd(orow + 1, gth[half] * acc[mt][q][half * 2 + 1]);
                    }
                }
            }
        }
    }
}

// ---------------------------------------------------------------------------
extern "C" void kernel_launch(void* const* d_in, const int* in_sizes, int n_in,
                              void* d_out, int out_size) {
    const float* x  = (const float*)d_in[0];   // (B,T,D)
    const float* rw = (const float*)d_in[1];   // (E,D)
    const float* w1 = (const float*)d_in[2];   // (E,D,H)
    const float* w2 = (const float*)d_in[3];   // (E,H,D)
    float* out = (float*)d_out;                // (B,T,D) fp32

    cudaFuncSetAttribute(gemm_mma<DD, 1, true>,  cudaFuncAttributeMaxDynamicSharedMemorySize, SMEM_GEMM);
    cudaFuncSetAttribute(gemm_mma<HH, 2, false>, cudaFuncAttributeMaxDynamicSharedMemorySize, SMEM_GEMM);

    int zblocks = out_size / (4 * 256);
    zero_kernel<<<zblocks, 256>>>((float4*)out);
    router_kernel<<<NN, 256>>>(x, rw);
    wsplit_kernel<DD, HH, 0><<<dim3(DD / 32, HH / 256, EE), 256>>>(w1);
    wsplit_kernel<HH, DD, 1><<<dim3(HH / 32, DD / 256, EE), 256>>>(w2);
    gather_kernel<<<dim3(NN, EE), 128>>>(x);
    gemm_mma<DD, 1, true><<<dim3(HH / TN, NN / TM, EE), 256, SMEM_GEMM>>>(nullptr);
    gemm_mma<HH, 2, false><<<dim3(DD / TN, NN / TM, EE * 2), 256, SMEM_GEMM>>>(out);
}

// round 16
// speedup vs baseline: 7.0142x; 1.0752x over previous
#include <cuda_runtime.h>
#include <cuda_bf16.h>
#include <cuda_fp16.h>
#include <cstdint>

// ---------------- problem constants ----------------
#define DD   1024
#define EE   8
#define HH   2048
#define NN   8192   // B*T tokens

// GEMM tile config: CTA 128x128, 8 warps (4M x 2N), warp tile 32x64, K-chunk 32
#define TM   128
#define TN   128
#define TK   32
// 1-pass stage: A8K + B8K = 16KB, 6 stages
#define B_OFF 8192
#define STAGE 16384
#define NST   6
#define SMEM_GEMM (NST*STAGE + 96)

// Tiled-plane geometry (all planes 8192B = 128 rows x 64B, swizzled):
//  row byte: m*64 + ((u ^ ((m>>1)&3))<<4) + (k&7)*2,  u = (k>>3)&3

// ---------------- static device scratch ----------------
__device__ int   g_cnt[EE];
__device__ int   g_tok[EE * NN];
__device__ float g_gate[EE * NN];
__device__ __half g_xg  [(size_t)EE * NN * DD];   // [e][mb<64][kc<32][8KB] fp16 single
__device__ __half g_h   [(size_t)EE * NN * HH];   // [e][mb<64][kc<64][8KB] fp16 single
__device__ __half g_w1t [(size_t)EE * DD * HH];   // [e][nb<16][kc<32][8KB] fp16 single
__device__ __half g_w2t [(size_t)EE * HH * DD];   // [e][nb<8][kc<64][8KB] fp16 single

// ---------------- helpers ----------------
__device__ __forceinline__ uint32_t smem_u32(const void* p) {
    uint32_t a;
    asm("{ .reg .u64 t; cvta.to.shared.u64 t, %1; cvt.u32.u64 %0, t; }" : "=r"(a) : "l"(p));
    return a;
}
__device__ __forceinline__ void ldsm4(uint32_t* r, uint32_t a) {
    asm volatile("ldmatrix.sync.aligned.m8n8.x4.shared.b16 {%0,%1,%2,%3}, [%4];"
                 : "=r"(r[0]), "=r"(r[1]), "=r"(r[2]), "=r"(r[3]) : "r"(a));
}
__device__ __forceinline__ void mma_f16(float* c, const uint32_t* a, uint32_t b0, uint32_t b1) {
    asm volatile("mma.sync.aligned.m16n8k16.row.col.f32.f16.f16.f32 "
                 "{%0,%1,%2,%3}, {%4,%5,%6,%7}, {%8,%9}, {%0,%1,%2,%3};"
                 : "+f"(c[0]), "+f"(c[1]), "+f"(c[2]), "+f"(c[3])
                 : "r"(a[0]), "r"(a[1]), "r"(a[2]), "r"(a[3]), "r"(b0), "r"(b1));
}
__device__ __forceinline__ uint32_t pack2h(float a, float b) {   // fp16 pair
    __half h0 = __float2half_rn(a), h1 = __float2half_rn(b);
    return (uint32_t)__half_as_ushort(h0) | ((uint32_t)__half_as_ushort(h1) << 16);
}
#define MBAR_INIT(a, c) asm volatile("mbarrier.init.shared.b64 [%0], %1;" :: "r"(a), "r"((uint32_t)(c)) : "memory")
#define MBAR_EXPECT_TX(a, tx) asm volatile("mbarrier.arrive.expect_tx.shared.b64 _, [%0], %1;" :: "r"(a), "r"((uint32_t)(tx)) : "memory")
#define MBAR_ARRIVE_REL(a) asm volatile("mbarrier.arrive.release.cta.shared::cta.b64 _, [%0];" :: "r"(a) : "memory")
#define MBAR_WAIT(a, ph) do { \
    uint32_t _m = (a); uint32_t _p = (uint32_t)(ph); uint32_t _d; \
    asm volatile("{\n\t.reg .pred p;\n\tmbarrier.try_wait.parity.acquire.cta.shared::cta.b64 p, [%1], %2;\n\tselp.b32 %0,1,0,p;\n\t}" \
        : "=r"(_d) : "r"(_m), "r"(_p) : "memory"); \
    if (!_d) { \
        asm volatile("{\n\t.reg .pred P1;\n\tWL_%=:\n\tmbarrier.try_wait.parity.acquire.cta.shared::cta.b64 P1, [%0], %1, 0x989680;\n\t@P1 bra.uni WD_%=;\n\tbra.uni WL_%=;\n\tWD_%=:\n\t}" \
            :: "r"(_m), "r"(_p) : "memory"); \
    } } while (0)
__device__ __forceinline__ void bulk_g2s(uint32_t dst, const void* src, uint32_t bytes, uint32_t mbar) {
    asm volatile("cp.async.bulk.shared::cta.global.mbarrier::complete_tx::bytes [%0], [%1], %2, [%3];"
                 :: "r"(dst), "l"(src), "r"(bytes), "r"(mbar) : "memory");
}

// ---------------------------------------------------------------------------
// Kernel 0: zero output + reset counters
// ---------------------------------------------------------------------------
__global__ void zero_kernel(float4* __restrict__ out) {
    int i = blockIdx.x * blockDim.x + threadIdx.x;
    out[i] = make_float4(0.f, 0.f, 0.f, 0.f);
    if (blockIdx.x == 0 && threadIdx.x < EE) g_cnt[threadIdx.x] = 0;
}

// ---------------------------------------------------------------------------
// Kernel 1: FUSED router + gather. One block (256 thr) per token.
// Computes logits/top-2/gates, then quantizes the x row (already in regs)
// straight into both chosen experts' swizzled A planes.
// Thread t holds x[4t..4t+3]; plane mapping: kc = t>>3, u = (t>>1)&3,
// halfunit = t&1 (8 bytes each).
// ---------------------------------------------------------------------------
__global__ __launch_bounds__(256) void router_gather_kernel(const float* __restrict__ x,
                                                            const float* __restrict__ rw) {
    int n = blockIdx.x, tid = threadIdx.x;
    float4 xv = ((const float4*)(x + (size_t)n * DD))[tid];

    float acc[EE];
#pragma unroll
    for (int e = 0; e < EE; e++) {
        float4 wv = ((const float4*)(rw + e * DD))[tid];
        acc[e] = xv.x * wv.x + xv.y * wv.y + xv.z * wv.z + xv.w * wv.w;
    }
#pragma unroll
    for (int e = 0; e < EE; e++)
#pragma unroll
        for (int o = 16; o > 0; o >>= 1) acc[e] += __shfl_down_sync(0xffffffffu, acc[e], o);

    __shared__ float sm[8][EE];
    __shared__ int   sres[4];   // e0, slot0, e1, slot1
    int warp = tid >> 5, lane = tid & 31;
    if (lane == 0)
#pragma unroll
        for (int e = 0; e < EE; e++) sm[warp][e] = acc[e];
    __syncthreads();

    if (tid == 0) {
        float logits[EE];
#pragma unroll
        for (int e = 0; e < EE; e++) {
            float s = 0.f;
#pragma unroll
            for (int w = 0; w < 8; w++) s += sm[w][e];
            logits[e] = s;
        }
        int i0 = 0; float v0 = logits[0];
#pragma unroll
        for (int e = 1; e < EE; e++) if (logits[e] > v0) { v0 = logits[e]; i0 = e; }
        int i1 = 0; float v1 = -3.0e38f;
#pragma unroll
        for (int e = 0; e < EE; e++) if (e != i0 && logits[e] > v1) { v1 = logits[e]; i1 = e; }
        float ex = __expf(v1 - v0);
        float g0 = 1.f / (1.f + ex);
        float g1 = ex * g0;
        int p0 = atomicAdd(&g_cnt[i0], 1);
        g_tok[i0 * NN + p0] = n;  g_gate[i0 * NN + p0] = g0;
        int p1 = atomicAdd(&g_cnt[i1], 1);
        g_tok[i1 * NN + p1] = n;  g_gate[i1 * NN + p1] = g1;
        sres[0] = i0; sres[1] = p0; sres[2] = i1; sres[3] = p1;
    }
    __syncthreads();

    uint2 hv;
    hv.x = pack2h(xv.x, xv.y);
    hv.y = pack2h(xv.z, xv.w);
    int kc = tid >> 3, u = (tid >> 1) & 3, hu = tid & 1;

#pragma unroll
    for (int k = 0; k < 2; k++) {
        int e    = sres[k * 2];
        int slot = sres[k * 2 + 1];
        int mb = slot >> 7, m = slot & 127;
        size_t plane = (((size_t)e * 64 + mb) * 32 + kc) * 8192;
        uint32_t off = (uint32_t)m * 64 + (uint32_t)((u ^ ((m >> 1) & 3)) << 4) + (uint32_t)(hu * 8);
        *(uint2*)((uint8_t*)g_xg + plane + off) = hv;
    }
}

// ---------------------------------------------------------------------------
// Kernel 2: zero padding rows [cnt, pad128) of each expert's A planes
// grid (EE), 256 threads
// ---------------------------------------------------------------------------
__global__ __launch_bounds__(256) void pad_kernel() {
    int e = blockIdx.x;
    int cnt = g_cnt[e];
    int pad = (cnt + 127) & ~127;  if (pad > NN) pad = NN;
    int tid = threadIdx.x;
    int kc = tid >> 3, u = (tid >> 1) & 3, hu = tid & 1;
    for (int slot = cnt + blockIdx.y; slot < pad; slot += gridDim.y) {
        int mb = slot >> 7, m = slot & 127;
        size_t plane = (((size_t)e * 64 + mb) * 32 + kc) * 8192;
        uint32_t off = (uint32_t)m * 64 + (uint32_t)((u ^ ((m >> 1) & 3)) << 4) + (uint32_t)(hu * 8);
        *(uint2*)((uint8_t*)g_xg + plane + off) = make_uint2(0, 0);
    }
}

// ---------------------------------------------------------------------------
// Kernels 3/4: weights -> transposed, single fp16 swizzled tiled B planes
// w [E][R][C] fp32 -> planes [E][nb=C/128][kc=R/32][8192B]
// grid (R/32, C/256, E), 256 threads
// ---------------------------------------------------------------------------
template<int R, int C, int WHICH>   // WHICH 0 -> g_w1t, 1 -> g_w2t
__global__ __launch_bounds__(256) void wsplit_kernel(const float* __restrict__ w) {
    int kc = blockIdx.x, nb2 = blockIdx.y, e = blockIdx.z;
    const float* src = w + (size_t)e * R * C;
    int t = threadIdx.x;
    int n = nb2 * 256 + t;
    float vals[32];
#pragma unroll
    for (int j = 0; j < 32; j++)
        vals[j] = src[(size_t)(kc * 32 + j) * C + n];
    __half* dst = (WHICH == 0) ? g_w1t : g_w2t;
    int nb = nb2 * 2 + (t >> 7);
    int m  = t & 127;
    size_t plane = (((size_t)e * (C / 128) + nb) * (R / 32) + kc) * 8192;
    int sw = (m >> 1) & 3;
    uint32_t rbase = (uint32_t)m * 64;
#pragma unroll
    for (int u = 0; u < 4; u++) {
        uint4 h4;
        h4.x = pack2h(vals[u*8+0], vals[u*8+1]);
        h4.y = pack2h(vals[u*8+2], vals[u*8+3]);
        h4.z = pack2h(vals[u*8+4], vals[u*8+5]);
        h4.w = pack2h(vals[u*8+6], vals[u*8+7]);
        uint32_t off = rbase + (uint32_t)((u ^ sw) << 4);
        *(uint4*)((uint8_t*)dst + plane + off) = h4;
    }
}

// ---------------------------------------------------------------------------
// 1-pass fp16 bulk-fed mma.sync grouped GEMM. occ 2, 6-stage mbarrier pipeline.
// D[128x128] += A * B^T. 256 threads (8 warps, 4Mx2N), warp tile 32x64.
// IS_G1: A = xg (K=1024), B = w1t; epilogue relu^2 -> g_h fp16.
// else:  A = g_h (K=2048, split-K 2), B = w2t; gate*atomicAdd scatter.
// ---------------------------------------------------------------------------
template<int KTOT, int KSLICES, bool IS_G1>
__global__ __launch_bounds__(256, 2) void gemm_mma(float* __restrict__ out) {
    constexpr int KC  = (KTOT / KSLICES) / TK;
    constexpr int NBP = (IS_G1 ? HH : DD) / 128;
    constexpr int KCB = KTOT / 32;
    int zz = blockIdx.z;
    int e = zz & (EE - 1);
    int slice = zz >> 3;
    int kc0 = slice * KC;
    int cnt = g_cnt[e];
    int m0  = blockIdx.y * TM;
    if (m0 >= cnt) return;
    int mb  = blockIdx.y;
    int nb  = blockIdx.x;
    int n0  = nb * TN;

    extern __shared__ char smem[];
    uint32_t sb = smem_u32(smem);
    uint32_t fullb  = sb + NST * STAGE;
    uint32_t emptyb = fullb + 48;

    const uint8_t *pA, *pB;
    {
        size_t ap = (((size_t)e * 64 + mb) * KCB) * 8192;
        size_t bp = (((size_t)e * NBP + nb) * KCB) * 8192;
        if (IS_G1) {
            pA = (const uint8_t*)g_xg + ap;
            pB = (const uint8_t*)g_w1t + bp;
        } else {
            pA = (const uint8_t*)g_h + ap;
            pB = (const uint8_t*)g_w2t + bp;
        }
    }

    int tid = threadIdx.x;
    int wid = tid >> 5, lane = tid & 31;

    if (tid == 0) {
#pragma unroll
        for (int s = 0; s < NST; s++) {
            MBAR_INIT(fullb + s * 8, 1);
            MBAR_INIT(emptyb + s * 8, 8);
        }
    }
    __syncthreads();

    auto issue = [&](int j, int s) {
        uint32_t st = sb + (uint32_t)s * STAGE;
        uint32_t mb_s = fullb + s * 8;
        size_t kc = (size_t)(kc0 + j);
        MBAR_EXPECT_TX(mb_s, STAGE);
        bulk_g2s(st,         pA + kc * 8192, 8192, mb_s);
        bulk_g2s(st + B_OFF, pB + kc * 8192, 8192, mb_s);
    };
    if (wid < NST && lane == 0 && wid < KC) issue(wid, wid);

    // ---- warp / lane geometry: 4 warps M x 2 warps N, warp tile 32x64 ----
    int wm = wid & 3;
    int wn = wid >> 2;
    int li = lane >> 3;
    int lr = lane & 7;
    int kadd = li >> 1;
    int rsel = (li & 1) * 8 + lr;

    uint32_t abase[2]; int asw[2];
#pragma unroll
    for (int mt = 0; mt < 2; mt++) {
        int m = wm * 32 + mt * 16 + rsel;
        abase[mt] = (uint32_t)m * 64;
        asw[mt] = (m >> 1) & 3;
    }
    uint32_t bbase[4]; int bsw[4];
#pragma unroll
    for (int p = 0; p < 4; p++) {
        int n = wn * 64 + p * 16 + rsel;
        bbase[p] = (uint32_t)n * 64;
        bsw[p] = (n >> 1) & 3;
    }

    float acc[2][8][4];
#pragma unroll
    for (int a = 0; a < 2; a++)
#pragma unroll
        for (int b = 0; b < 8; b++)
#pragma unroll
            for (int c = 0; c < 4; c++) acc[a][b][c] = 0.f;

    int s = 0;
    uint32_t ph = 0;
    for (int j = 0; j < KC; j++) {
        MBAR_WAIT(fullb + s * 8, ph);
        uint32_t st = sb + (uint32_t)s * STAGE;
#pragma unroll
        for (int kqi = 0; kqi < 2; kqi++) {
            int kq = kqi * 2;
            uint32_t ar[2][4];
#pragma unroll
            for (int mt = 0; mt < 2; mt++) {
                uint32_t off = abase[mt] + (uint32_t)((((kq + kadd) ^ asw[mt])) << 4);
                ldsm4(ar[mt], st + off);
            }
#pragma unroll
            for (int p = 0; p < 4; p++) {
                uint32_t bh[4];
                uint32_t off = bbase[p] + (uint32_t)((((kq + kadd) ^ bsw[p])) << 4);
                ldsm4(bh, st + B_OFF + off);
                if (kqi == 1 && p == 3 && lane == 0) MBAR_ARRIVE_REL(emptyb + s * 8);
#pragma unroll
                for (int mt = 0; mt < 2; mt++) {
#pragma unroll
                    for (int sgl = 0; sgl < 2; sgl++) {
                        float* c = acc[mt][p * 2 + sgl];
                        mma_f16(c, ar[mt], bh[sgl], bh[2 + sgl]);
                    }
                }
            }
        }
        if (wid == s && lane == 0 && j + NST < KC) {
            MBAR_WAIT(emptyb + s * 8, ph);
            issue(j + NST, s);
        }
        if (++s == NST) { s = 0; ph ^= 1; }
    }

    // ---- epilogue ----
    int r4 = lane >> 2, cpair = (lane & 3) * 2;
    if (IS_G1) {
        size_t planeH0 = (((size_t)e * 64 + mb) * 64) * 8192;
#pragma unroll
        for (int mt = 0; mt < 2; mt++) {
#pragma unroll
            for (int q = 0; q < 8; q++) {
                int kcH = (n0 >> 5) + wn * 2 + (q >> 2);
                int u = q & 3;
#pragma unroll
                for (int half = 0; half < 2; half++) {
                    int lm = wm * 32 + mt * 16 + r4 + half * 8;
                    float v0 = acc[mt][q][half * 2 + 0];
                    float v1 = acc[mt][q][half * 2 + 1];
                    v0 = fmaxf(v0, 0.f); v0 *= v0;
                    v1 = fmaxf(v1, 0.f); v1 *= v1;
                    uint32_t hw = pack2h(v0, v1);
                    size_t off = planeH0 + (size_t)kcH * 8192 +
                                 (uint32_t)(lm * 64 + ((u ^ ((lm >> 1) & 3)) << 4) + cpair * 2);
                    *(uint32_t*)((uint8_t*)g_h + off) = hw;
                }
            }
        }
    } else {
#pragma unroll
        for (int mt = 0; mt < 2; mt++) {
            int gm = m0 + wm * 32 + mt * 16;
            int   tokh[2];
            float gth[2];
#pragma unroll
            for (int half = 0; half < 2; half++) {
                int slot = gm + r4 + half * 8;
                bool ok = slot < cnt;
                tokh[half] = ok ? g_tok[e * NN + slot] : -1;
                gth[half]  = ok ? g_gate[e * NN + slot] : 0.f;
            }
#pragma unroll
            for (int q = 0; q < 8; q++) {
                int gn = n0 + wn * 64 + q * 8 + cpair;
#pragma unroll
                for (int half = 0; half < 2; half++) {
                    if (tokh[half] >= 0) {
                        float* orow = out + (size_t)tokh[half] * DD + gn;
                        atomicAdd(orow,     gth[half] * acc[mt][q][half * 2 + 0]);
                        atomicAdd(orow + 1, gth[half] * acc[mt][q][half * 2 + 1]);
                    }
                }
            }
        }
    }
}

// ---------------------------------------------------------------------------
extern "C" void kernel_launch(void* const* d_in, const int* in_sizes, int n_in,
                              void* d_out, int out_size) {
    const float* x  = (const float*)d_in[0];   // (B,T,D)
    const float* rw = (const float*)d_in[1];   // (E,D)
    const float* w1 = (const float*)d_in[2];   // (E,D,H)
    const float* w2 = (const float*)d_in[3];   // (E,H,D)
    float* out = (float*)d_out;                // (B,T,D) fp32

    cudaFuncSetAttribute(gemm_mma<DD, 1, true>,  cudaFuncAttributeMaxDynamicSharedMemorySize, SMEM_GEMM);
    cudaFuncSetAttribute(gemm_mma<HH, 2, false>, cudaFuncAttributeMaxDynamicSharedMemorySize, SMEM_GEMM);

    int zblocks = out_size / (4 * 256);
    zero_kernel<<<zblocks, 256>>>((float4*)out);
    router_gather_kernel<<<NN, 256>>>(x, rw);
    pad_kernel<<<dim3(EE, 16), 256>>>();
    wsplit_kernel<DD, HH, 0><<<dim3(DD / 32, HH / 256, EE), 256>>>(w1);
    wsplit_kernel<HH, DD, 1><<<dim3(HH / 32, DD / 256, EE), 256>>>(w2);
    gemm_mma<DD, 1, true><<<dim3(HH / TN, NN / TM, EE), 256, SMEM_GEMM>>>(nullptr);
    gemm_mma<HH, 2, false><<<dim3(DD / TN, NN / TM, EE * 2), 256, SMEM_GEMM>>>(out);
}